// round 7
// baseline (speedup 1.0000x reference)
#include <cuda_runtime.h>
#include <cuda_bf16.h>
#include <math.h>
#include <cstdint>

// ---------------- problem constants ----------------
#define N_NODES 50000
#define N_EDGES 600000
#define N_PRED  200000
#define ETOT    (N_EDGES + N_NODES)
#define W1      512
#define W2      256
#define H1      4
#define H2      2
#define K1      128
#define K2      512
#define BN_EPS  1e-5f

// ---------------- scratch (device globals) ----------------
__device__ float g_xl1[(size_t)N_NODES * W1];
__device__ float g_xr1[(size_t)N_NODES * W1];
__device__ float g_xl2[(size_t)N_NODES * W2];
__device__ float g_xr2[(size_t)N_NODES * W2];
__device__ float g_z  [(size_t)N_NODES * W2];

__device__ __nv_bfloat16 g_As1[(size_t)N_NODES * (2 * K1)];   // [a0|a1]
__device__ __nv_bfloat16 g_As2[(size_t)N_NODES * (2 * K2)];   // [a0|a1]
__device__ __nv_bfloat16 g_Wc1s[(2 * W1) * (3 * K1)];         // rows [Wl|Wr], cols [b0|b0|b1]
__device__ __nv_bfloat16 g_Wc2s[(2 * W2) * (3 * K2)];

__device__ float g_bc1[2 * W1];
__device__ float g_bc2[2 * W2];

__device__ int g_deg[N_NODES];
__device__ int g_off[N_NODES + 1];
__device__ int g_cursor[N_NODES];
__device__ int g_csr_src[ETOT];

__device__ float g_bns1[W1];
__device__ float g_bnt1[W1];
__device__ float g_bns2[W2];
__device__ float g_bnt2[W2];

// ---------------- helpers ----------------
__device__ __forceinline__ uint32_t smem_to_u32(const void* p) {
    uint32_t a;
    asm("{ .reg .u64 t; cvta.to.shared.u64 t, %1; cvt.u32.u64 %0, t; }" : "=r"(a) : "l"(p));
    return a;
}
#define SWZ128(b) ((b) ^ (((b) >> 3) & 0x70))

__device__ __forceinline__ void ldmatrix_x4(uint32_t* r, uint32_t addr) {
    asm volatile("ldmatrix.sync.aligned.m8n8.x4.shared.b16 {%0,%1,%2,%3}, [%4];"
                 : "=r"(r[0]), "=r"(r[1]), "=r"(r[2]), "=r"(r[3]) : "r"(addr));
}
__device__ __forceinline__ void mma16816(float* c, const uint32_t* a,
                                         uint32_t b0, uint32_t b1) {
    asm volatile("mma.sync.aligned.m16n8k16.row.col.f32.bf16.bf16.f32 "
                 "{%0,%1,%2,%3}, {%4,%5,%6,%7}, {%8,%9}, {%0,%1,%2,%3};"
                 : "+f"(c[0]), "+f"(c[1]), "+f"(c[2]), "+f"(c[3])
                 : "r"(a[0]), "r"(a[1]), "r"(a[2]), "r"(a[3]), "r"(b0), "r"(b1));
}

// ---------------- prep kernels ----------------
__global__ void split_A(const float* __restrict__ X, __nv_bfloat16* __restrict__ out,
                        int M, int K) {
    int idx = blockIdx.x * blockDim.x + threadIdx.x;
    if (idx >= M * K) return;
    int m = idx / K, k = idx - m * K;
    float a = X[idx];
    __nv_bfloat16 a0 = __float2bfloat16(a);
    __nv_bfloat16 a1 = __float2bfloat16(a - __bfloat162float(a0));
    size_t base = (size_t)m * (2 * K);
    out[base + k] = a0;
    out[base + K + k] = a1;
}

__global__ void split_W_pair(const float* __restrict__ Wl, const float* __restrict__ Wr,
                             __nv_bfloat16* __restrict__ out, int K, int Nn) {
    int idx = blockIdx.x * blockDim.x + threadIdx.x;
    if (idx >= 2 * K * Nn) return;
    const float* W = (idx < K * Nn) ? Wl : Wr;
    int rem = (idx < K * Nn) ? idx : idx - K * Nn;
    int noff = (idx < K * Nn) ? 0 : Nn;
    int k = rem / Nn, n = rem - k * Nn;
    float b = W[rem];
    __nv_bfloat16 b0 = __float2bfloat16(b);
    __nv_bfloat16 b1 = __float2bfloat16(b - __bfloat162float(b0));
    size_t base = (size_t)(n + noff) * (3 * K);
    out[base + k] = b0;
    out[base + K + k] = b0;
    out[base + 2 * K + k] = b1;
}

__global__ void cat2(const float* __restrict__ a, const float* __restrict__ b,
                     float* __restrict__ o, int n) {
    int i = blockIdx.x * blockDim.x + threadIdx.x;
    if (i < n) { o[i] = a[i]; o[n + i] = b[i]; }
}

// ---------------- HMMA bf16 GEMM ----------------
// C = A'[M,KsA] (chunk-remapped to KsB) @ B''[Nn,KsB]^T + bias
// CTA tile 128x256, warp tile 64x64 (8 warps, 2x4), K-chunk 64, 3-stage cp.async.
// Output split: cols [0,Wn) -> Cl, [Wn,2Wn) -> Cr (compact, row stride Wn).
#define STAGE_BYTES 49152   // 16KB A + 32KB B
#define SMB_OFF 16384

__global__ __launch_bounds__(256, 1)
void gemm_mma(const __nv_bfloat16* __restrict__ A, const __nv_bfloat16* __restrict__ B,
              const float* __restrict__ bias, float* __restrict__ Cl,
              float* __restrict__ Cr,
              int M, int KsA, int KsB, int Nn, int Wn) {
    extern __shared__ __align__(1024) char sm[];
    int tid = threadIdx.x;
    int wid = tid >> 5, lane = tid & 31;
    int m0 = blockIdx.y * 128, n0 = blockIdx.x * 256;
    int wm = wid >> 2, wn = wid & 3;     // warp tile: rows 64*wm, cols 64*wn
    uint32_t smb = smem_to_u32(sm);

    float acc[4][8][4];
#pragma unroll
    for (int t = 0; t < 4; t++)
#pragma unroll
        for (int j = 0; j < 8; j++)
#pragma unroll
            for (int q = 0; q < 4; q++) acc[t][j][q] = 0.f;

    int nch = KsB / 64;
    int nchA = KsA / 64;

    auto issue_load = [&](int c, int s) {
        uint32_t base = smb + s * STAGE_BYTES;
        int ca = (c < nchA) ? c : c - nchA;   // reuse a0 chunks for the b1 section
#pragma unroll
        for (int r = 0; r < 4; r++) {
            int idx = tid + r * 256;
            int row = idx >> 3, j = idx & 7;
            const __nv_bfloat16* gp = A + (size_t)(m0 + row) * KsA + ca * 64 + j * 8;
            uint32_t sa = base + SWZ128(row * 128 + j * 16);
            int sz = (m0 + row < M) ? 16 : 0;
            asm volatile("cp.async.cg.shared.global [%0], [%1], 16, %2;"
                         :: "r"(sa), "l"(gp), "r"(sz));
        }
#pragma unroll
        for (int r = 0; r < 8; r++) {
            int idx = tid + r * 256;
            int row = idx >> 3, j = idx & 7;
            const __nv_bfloat16* gp = B + (size_t)(n0 + row) * KsB + c * 64 + j * 8;
            uint32_t sa = base + SMB_OFF + SWZ128(row * 128 + j * 16);
            asm volatile("cp.async.cg.shared.global [%0], [%1], 16;"
                         :: "r"(sa), "l"(gp));
        }
        asm volatile("cp.async.commit_group;");
    };

    issue_load(0, 0);
    if (nch > 1) issue_load(1, 1);

    for (int c = 0; c < nch; c++) {
        if (c + 1 < nch) asm volatile("cp.async.wait_group 1;");
        else             asm volatile("cp.async.wait_group 0;");
        __syncthreads();
        if (c + 2 < nch) issue_load(c + 2, (c + 2) % 3);

        uint32_t ab = smb + (c % 3) * STAGE_BYTES;
        uint32_t bb = ab + SMB_OFF;
#pragma unroll
        for (int kk = 0; kk < 4; kk++) {
            uint32_t af[4][4];
#pragma unroll
            for (int t = 0; t < 4; t++) {
                int rl = 64 * wm + 16 * t + (lane & 15);
                uint32_t ad = ab + SWZ128(rl * 128 + kk * 32 + (lane >> 4) * 16);
                ldmatrix_x4(af[t], ad);
            }
            uint32_t bf[4][4];
#pragma unroll
            for (int p = 0; p < 4; p++) {
                int nl = 64 * wn + 16 * p + ((lane >> 4) << 3) + (lane & 7);
                uint32_t bd = bb + SWZ128(nl * 128 + kk * 32 + ((lane >> 3) & 1) * 16);
                ldmatrix_x4(bf[p], bd);
            }
#pragma unroll
            for (int t = 0; t < 4; t++)
#pragma unroll
                for (int j = 0; j < 8; j++)
                    mma16816(acc[t][j], af[t],
                             bf[j >> 1][(j & 1) * 2], bf[j >> 1][(j & 1) * 2 + 1]);
        }
    }

    // epilogue: split into compact Cl / Cr (warp's 64-col block never straddles Wn)
    int cbase = n0 + 64 * wn;
    float* Cd = (cbase < Wn) ? Cl : Cr;
    int coff = (cbase < Wn) ? cbase : cbase - Wn;
#pragma unroll
    for (int t = 0; t < 4; t++) {
        int gr = m0 + 64 * wm + 16 * t + (lane >> 2);
#pragma unroll
        for (int j = 0; j < 8; j++) {
            int gc = coff + 8 * j + (lane & 3) * 2;
            float2 bi = *(const float2*)(bias + cbase + 8 * j + (lane & 3) * 2);
            if (gr < M) {
                float2 o = make_float2(acc[t][j][0] + bi.x, acc[t][j][1] + bi.y);
                *(float2*)(Cd + (size_t)gr * Wn + gc) = o;
            }
            if (gr + 8 < M) {
                float2 o = make_float2(acc[t][j][2] + bi.x, acc[t][j][3] + bi.y);
                *(float2*)(Cd + (size_t)(gr + 8) * Wn + gc) = o;
            }
        }
    }
}

// ---------------- BN prep ----------------
__global__ void bn_prep(const float* __restrict__ bias, const float* __restrict__ g,
                        const float* __restrict__ b, const float* __restrict__ m,
                        const float* __restrict__ v, float* __restrict__ s,
                        float* __restrict__ t, int n) {
    int i = blockIdx.x * blockDim.x + threadIdx.x;
    if (i < n) {
        float sc = g[i] * rsqrtf(v[i] + BN_EPS);
        s[i] = sc;
        t[i] = b[i] + (bias[i] - m[i]) * sc;
    }
}

// ---------------- CSR build ----------------
__global__ void deg_zero(int* deg) {
    int i = blockIdx.x * blockDim.x + threadIdx.x;
    if (i < N_NODES) deg[i] = 0;
}
__global__ void deg_hist(const int* __restrict__ ei, int* __restrict__ deg) {
    int i = blockIdx.x * blockDim.x + threadIdx.x;
    if (i >= ETOT) return;
    int dst = (i < N_EDGES) ? ei[N_EDGES + i] : (i - N_EDGES);
    atomicAdd(&deg[dst], 1);
}
__global__ void scan_kernel(const int* __restrict__ deg, int* __restrict__ off,
                            int* __restrict__ cursor) {
    __shared__ int warp_sums[32];
    const int T = 1024;
    int tid = threadIdx.x;
    int chunk = (N_NODES + T - 1) / T;
    int start = tid * chunk;
    int end = min(start + chunk, N_NODES);
    int local = 0;
    for (int i = start; i < end; i++) local += deg[i];
    int lane = tid & 31, wid = tid >> 5;
    int v = local;
#pragma unroll
    for (int o = 1; o < 32; o <<= 1) {
        int u = __shfl_up_sync(0xFFFFFFFFu, v, o);
        if (lane >= o) v += u;
    }
    if (lane == 31) warp_sums[wid] = v;
    __syncthreads();
    if (wid == 0) {
        int s = warp_sums[lane];
#pragma unroll
        for (int o = 1; o < 32; o <<= 1) {
            int u = __shfl_up_sync(0xFFFFFFFFu, s, o);
            if (lane >= o) s += u;
        }
        warp_sums[lane] = s;
    }
    __syncthreads();
    int excl = v - local + (wid > 0 ? warp_sums[wid - 1] : 0);
    int run = excl;
    for (int i = start; i < end; i++) {
        off[i] = run;
        cursor[i] = run;
        run += deg[i];
    }
    if (tid == T - 1) off[N_NODES] = run;
}
__global__ void csr_scatter(const int* __restrict__ ei, int* __restrict__ cursor,
                            int* __restrict__ csr_src) {
    int i = blockIdx.x * blockDim.x + threadIdx.x;
    if (i >= ETOT) return;
    int src, dst;
    if (i < N_EDGES) { src = ei[i]; dst = ei[N_EDGES + i]; }
    else             { src = dst = i - N_EDGES; }
    int pos = atomicAdd(&cursor[dst], 1);
    csr_src[pos] = src;
}

// ---------------- fused GATv2 aggregation (one warp per dst node) --------------
template<int H, bool OUTBF16>
__global__ __launch_bounds__(256)
void fused_agg(const float* __restrict__ xl, const float* __restrict__ xr,
               const float* __restrict__ att,
               const int* __restrict__ off, const int* __restrict__ csr_src,
               const float* __restrict__ bns, const float* __restrict__ bnt,
               void* __restrict__ outp) {
    int node = (blockIdx.x * blockDim.x + threadIdx.x) >> 5;
    int lane = threadIdx.x & 31;
    if (node >= N_NODES) return;
    const int Wd = H * 128;

    const float4* xr4 = (const float4*)(xr + (size_t)node * Wd);
    const float4* at4 = (const float4*)att;

    float4 xrr[H], attr[H], acc[H];
    float m[H], sum[H];
#pragma unroll
    for (int h = 0; h < H; h++) {
        xrr[h]  = xr4[h * 32 + lane];
        attr[h] = at4[h * 32 + lane];
        acc[h]  = make_float4(0.f, 0.f, 0.f, 0.f);
        m[h]    = -INFINITY;
        sum[h]  = 0.f;
    }

    int e0 = off[node], e1 = off[node + 1];
    int src = csr_src[e0];
    float4 v[H];
    {
        const float4* xs = (const float4*)(xl + (size_t)src * Wd);
#pragma unroll
        for (int h = 0; h < H; h++) v[h] = xs[h * 32 + lane];
    }

    for (int e = e0; e < e1; e++) {
        int nsrc = (e + 1 < e1) ? csr_src[e + 1] : src;
        const float4* xn = (const float4*)(xl + (size_t)nsrc * Wd);
        float4 vn[H];
#pragma unroll
        for (int h = 0; h < H; h++) vn[h] = xn[h * 32 + lane];

#pragma unroll
        for (int h = 0; h < H; h++) {
            float ex = v[h].x + xrr[h].x; ex = ex > 0.f ? ex : 0.2f * ex;
            float ey = v[h].y + xrr[h].y; ey = ey > 0.f ? ey : 0.2f * ey;
            float ez = v[h].z + xrr[h].z; ez = ez > 0.f ? ez : 0.2f * ez;
            float ew = v[h].w + xrr[h].w; ew = ew > 0.f ? ew : 0.2f * ew;
            float s = ex * attr[h].x + ey * attr[h].y + ez * attr[h].z + ew * attr[h].w;
#pragma unroll
            for (int o = 16; o > 0; o >>= 1) s += __shfl_xor_sync(0xFFFFFFFFu, s, o);

            float mn = fmaxf(m[h], s);
            float c  = __expf(m[h] - mn);
            float p  = __expf(s - mn);
            sum[h]   = sum[h] * c + p;
            acc[h].x = acc[h].x * c + p * v[h].x;
            acc[h].y = acc[h].y * c + p * v[h].y;
            acc[h].z = acc[h].z * c + p * v[h].z;
            acc[h].w = acc[h].w * c + p * v[h].w;
            m[h] = mn;
        }
#pragma unroll
        for (int h = 0; h < H; h++) v[h] = vn[h];
    }

#pragma unroll
    for (int h = 0; h < H; h++) {
        int cbase = h * 128 + lane * 4;
        float4 sc = *(const float4*)(bns + cbase);
        float4 tt = *(const float4*)(bnt + cbase);
        float inv = 1.f / sum[h];
        float4 o;
        o.x = fmaxf(fmaf(acc[h].x * inv, sc.x, tt.x), 0.f);
        o.y = fmaxf(fmaf(acc[h].y * inv, sc.y, tt.y), 0.f);
        o.z = fmaxf(fmaf(acc[h].z * inv, sc.z, tt.z), 0.f);
        o.w = fmaxf(fmaf(acc[h].w * inv, sc.w, tt.w), 0.f);
        if (OUTBF16) {
            __nv_bfloat16* out = (__nv_bfloat16*)outp;
            size_t base = (size_t)node * (2 * Wd);
            __nv_bfloat16 h0x = __float2bfloat16(o.x), h0y = __float2bfloat16(o.y);
            __nv_bfloat16 h0z = __float2bfloat16(o.z), h0w = __float2bfloat16(o.w);
            __nv_bfloat16 h1x = __float2bfloat16(o.x - __bfloat162float(h0x));
            __nv_bfloat16 h1y = __float2bfloat16(o.y - __bfloat162float(h0y));
            __nv_bfloat16 h1z = __float2bfloat16(o.z - __bfloat162float(h0z));
            __nv_bfloat16 h1w = __float2bfloat16(o.w - __bfloat162float(h0w));
            uint2 p0, p1;
            p0.x = ((uint32_t)__bfloat16_as_ushort(h0y) << 16) | __bfloat16_as_ushort(h0x);
            p0.y = ((uint32_t)__bfloat16_as_ushort(h0w) << 16) | __bfloat16_as_ushort(h0z);
            p1.x = ((uint32_t)__bfloat16_as_ushort(h1y) << 16) | __bfloat16_as_ushort(h1x);
            p1.y = ((uint32_t)__bfloat16_as_ushort(h1w) << 16) | __bfloat16_as_ushort(h1z);
            *(uint2*)(out + base + cbase) = p0;
            *(uint2*)(out + base + Wd + cbase) = p1;
        } else {
            float* out = (float*)outp;
            *(float4*)(out + (size_t)node * Wd + cbase) = o;
        }
    }
}

// ---------------- prediction head ----------------
__global__ void head_kernel(const float* __restrict__ z, const int* __restrict__ pe,
                            const float* __restrict__ pr, const float* __restrict__ pert,
                            const float* __restrict__ Wp, const float* __restrict__ bp,
                            float* __restrict__ out) {
    __shared__ float sw[(W2 * 2 + 3) * 2];
    for (int i = threadIdx.x; i < (W2 * 2 + 3) * 2; i += blockDim.x) sw[i] = Wp[i];
    __syncthreads();

    int w = (blockIdx.x * blockDim.x + threadIdx.x) >> 5;
    int lane = threadIdx.x & 31;
    if (w >= N_PRED) return;
    int s = pe[w], d = pe[N_PRED + w];
    const float4* zs = (const float4*)(z + (size_t)s * W2);
    const float4* zd = (const float4*)(z + (size_t)d * W2);

    float a0 = 0.f, a1 = 0.f;
#pragma unroll
    for (int q = 0; q < 2; q++) {
        int r = lane * 2 + q;
        float4 vz = zs[r];
        int base = (r * 4) * 2;
        a0 += vz.x * sw[base] + vz.y * sw[base + 2] + vz.z * sw[base + 4] + vz.w * sw[base + 6];
        a1 += vz.x * sw[base + 1] + vz.y * sw[base + 3] + vz.z * sw[base + 5] + vz.w * sw[base + 7];
        float4 vd = zd[r];
        int base2 = (W2 + r * 4) * 2;
        a0 += vd.x * sw[base2] + vd.y * sw[base2 + 2] + vd.z * sw[base2 + 4] + vd.w * sw[base2 + 6];
        a1 += vd.x * sw[base2 + 1] + vd.y * sw[base2 + 3] + vd.z * sw[base2 + 5] + vd.w * sw[base2 + 7];
    }
    if (lane == 0) {
        float prs = pr[s], prd = pr[d], pp = pert[s] * pert[d];
        int b0 = (2 * W2) * 2;
        a0 += prs * sw[b0] + prd * sw[b0 + 2] + pp * sw[b0 + 4];
        a1 += prs * sw[b0 + 1] + prd * sw[b0 + 3] + pp * sw[b0 + 5];
    }
#pragma unroll
    for (int o = 16; o > 0; o >>= 1) {
        a0 += __shfl_xor_sync(0xFFFFFFFFu, a0, o);
        a1 += __shfl_xor_sync(0xFFFFFFFFu, a1, o);
    }
    if (lane == 0) {
        out[(size_t)w * 2 + 0] = a0 + bp[0];
        out[(size_t)w * 2 + 1] = a1 + bp[1];
    }
}

// ---------------- launch ----------------
extern "C" void kernel_launch(void* const* d_in, const int* in_sizes, int n_in,
                              void* d_out, int out_size) {
    const float* x     = (const float*)d_in[0];
    const int*   ei    = (const int*)d_in[1];
    const int*   pe    = (const int*)d_in[2];
    const float* pert  = (const float*)d_in[3];
    const float* pr    = (const float*)d_in[4];
    const float* Wl1   = (const float*)d_in[5];
    const float* bl1   = (const float*)d_in[6];
    const float* Wr1   = (const float*)d_in[7];
    const float* br1   = (const float*)d_in[8];
    const float* att1  = (const float*)d_in[9];
    const float* bias1 = (const float*)d_in[10];
    const float* bn1g  = (const float*)d_in[11];
    const float* bn1b  = (const float*)d_in[12];
    const float* bn1m  = (const float*)d_in[13];
    const float* bn1v  = (const float*)d_in[14];
    const float* Wl2   = (const float*)d_in[15];
    const float* bl2   = (const float*)d_in[16];
    const float* Wr2   = (const float*)d_in[17];
    const float* br2   = (const float*)d_in[18];
    const float* att2  = (const float*)d_in[19];
    const float* bias2 = (const float*)d_in[20];
    const float* bn2g  = (const float*)d_in[21];
    const float* bn2b  = (const float*)d_in[22];
    const float* bn2m  = (const float*)d_in[23];
    const float* bn2v  = (const float*)d_in[24];
    const float* Wp    = (const float*)d_in[25];
    const float* bp    = (const float*)d_in[26];
    float* out = (float*)d_out;

    float *xl1, *xr1, *xl2, *xr2, *z, *bc1, *bc2;
    float *bns1, *bnt1, *bns2, *bnt2;
    int *deg, *off, *cursor, *csr_src;
    __nv_bfloat16 *As1, *As2, *Wc1s, *Wc2s;
    cudaGetSymbolAddress((void**)&xl1, g_xl1);
    cudaGetSymbolAddress((void**)&xr1, g_xr1);
    cudaGetSymbolAddress((void**)&xl2, g_xl2);
    cudaGetSymbolAddress((void**)&xr2, g_xr2);
    cudaGetSymbolAddress((void**)&z,  g_z);
    cudaGetSymbolAddress((void**)&bc1, g_bc1);
    cudaGetSymbolAddress((void**)&bc2, g_bc2);
    cudaGetSymbolAddress((void**)&bns1, g_bns1);
    cudaGetSymbolAddress((void**)&bnt1, g_bnt1);
    cudaGetSymbolAddress((void**)&bns2, g_bns2);
    cudaGetSymbolAddress((void**)&bnt2, g_bnt2);
    cudaGetSymbolAddress((void**)&deg, g_deg);
    cudaGetSymbolAddress((void**)&off, g_off);
    cudaGetSymbolAddress((void**)&cursor, g_cursor);
    cudaGetSymbolAddress((void**)&csr_src, g_csr_src);
    cudaGetSymbolAddress((void**)&As1, g_As1);
    cudaGetSymbolAddress((void**)&As2, g_As2);
    cudaGetSymbolAddress((void**)&Wc1s, g_Wc1s);
    cudaGetSymbolAddress((void**)&Wc2s, g_Wc2s);

    static int smem_cfg = 0;
    if (!smem_cfg) {
        cudaFuncSetAttribute(gemm_mma, cudaFuncAttributeMaxDynamicSharedMemorySize,
                             3 * STAGE_BYTES);
        smem_cfg = 1;
    }

    const int TB = 256;
    int mblk = (N_NODES + 127) / 128;              // 391
    int nwarp_blk = (N_NODES * 32 + TB - 1) / TB;

    // ---- layer-1 prep + GEMM (gemm is launch #4 for profiling) ----
    cat2<<<(W1 + 255) / 256, 256>>>(bl1, br1, bc1, W1);
    split_A<<<(N_NODES * K1 + TB - 1) / TB, TB>>>(x, As1, N_NODES, K1);
    split_W_pair<<<(2 * K1 * W1 + TB - 1) / TB, TB>>>(Wl1, Wr1, Wc1s, K1, W1);
    {
        dim3 g1((2 * W1) / 256, mblk);
        gemm_mma<<<g1, 256, 3 * STAGE_BYTES>>>(As1, Wc1s, bc1, xl1, xr1,
                                               N_NODES, 2 * K1, 3 * K1, 2 * W1, W1);
    }

    // ---- CSR build + BN folding + layer-2 prep ----
    deg_zero<<<(N_NODES + TB - 1) / TB, TB>>>(deg);
    deg_hist<<<(ETOT + TB - 1) / TB, TB>>>(ei, deg);
    scan_kernel<<<1, 1024>>>(deg, off, cursor);
    csr_scatter<<<(ETOT + TB - 1) / TB, TB>>>(ei, cursor, csr_src);
    bn_prep<<<(W1 + 255) / 256, 256>>>(bias1, bn1g, bn1b, bn1m, bn1v, bns1, bnt1, W1);
    bn_prep<<<(W2 + 255) / 256, 256>>>(bias2, bn2g, bn2b, bn2m, bn2v, bns2, bnt2, W2);
    cat2<<<(W2 + 255) / 256, 256>>>(bl2, br2, bc2, W2);
    split_W_pair<<<(2 * K2 * W2 + TB - 1) / TB, TB>>>(Wl2, Wr2, Wc2s, K2, W2);

    // ---- layer-1 aggregation -> bf16 [a0|a1] for layer-2 GEMM ----
    fused_agg<H1, true><<<nwarp_blk, TB>>>(xl1, xr1, att1,
                                           off, csr_src, bns1, bnt1, As2);

    // ---- layer 2 ----
    {
        dim3 g2((2 * W2) / 256, mblk);
        gemm_mma<<<g2, 256, 3 * STAGE_BYTES>>>(As2, Wc2s, bc2, xl2, xr2,
                                               N_NODES, 2 * K2, 3 * K2, 2 * W2, W2);
    }
    fused_agg<H2, false><<<nwarp_blk, TB>>>(xl2, xr2, att2,
                                            off, csr_src, bns2, bnt2, z);

    // ---- head ----
    head_kernel<<<(N_PRED * 32 + TB - 1) / TB, TB>>>(z, pe, pr, pert, Wp, bp, out);
}

// round 8
// speedup vs baseline: 1.0410x; 1.0410x over previous
#include <cuda_runtime.h>
#include <cuda_bf16.h>
#include <math.h>
#include <cstdint>

// ---------------- problem constants ----------------
#define N_NODES 50000
#define N_EDGES 600000
#define N_PRED  200000
#define ETOT    (N_EDGES + N_NODES)
#define W1      512
#define W2      256
#define H1      4
#define H2      2
#define K1      128
#define K2      512
#define BN_EPS  1e-5f

// ---------------- scratch (device globals) ----------------
__device__ float g_xl1[(size_t)N_NODES * W1];
__device__ float g_xr1[(size_t)N_NODES * W1];
__device__ float g_xl2[(size_t)N_NODES * W2];
__device__ float g_xr2[(size_t)N_NODES * W2];
__device__ float g_z  [(size_t)N_NODES * W2];

__device__ __nv_bfloat16 g_As1[(size_t)N_NODES * (2 * K1)];   // [a0|a1]
__device__ __nv_bfloat16 g_As2[(size_t)N_NODES * (2 * K2)];   // [a0|a1]
__device__ __nv_bfloat16 g_Wc1s[(2 * W1) * (3 * K1)];         // rows [Wl|Wr], cols [b0|b0|b1]
__device__ __nv_bfloat16 g_Wc2s[(2 * W2) * (3 * K2)];

__device__ float g_bc1[2 * W1];
__device__ float g_bc2[2 * W2];

__device__ int g_deg[N_NODES];
__device__ int g_off[N_NODES + 1];
__device__ int g_cursor[N_NODES];
__device__ int g_csr_src[ETOT];

__device__ float g_bns1[W1];
__device__ float g_bnt1[W1];
__device__ float g_bns2[W2];
__device__ float g_bnt2[W2];

// ---------------- helpers ----------------
__device__ __forceinline__ uint32_t smem_to_u32(const void* p) {
    uint32_t a;
    asm("{ .reg .u64 t; cvta.to.shared.u64 t, %1; cvt.u32.u64 %0, t; }" : "=r"(a) : "l"(p));
    return a;
}
#define SWZ128(b) ((b) ^ (((b) >> 3) & 0x70))

__device__ __forceinline__ void ldmatrix_x4(uint32_t* r, uint32_t addr) {
    asm volatile("ldmatrix.sync.aligned.m8n8.x4.shared.b16 {%0,%1,%2,%3}, [%4];"
                 : "=r"(r[0]), "=r"(r[1]), "=r"(r[2]), "=r"(r[3]) : "r"(addr));
}
__device__ __forceinline__ void mma16816(float* c, const uint32_t* a,
                                         uint32_t b0, uint32_t b1) {
    asm volatile("mma.sync.aligned.m16n8k16.row.col.f32.bf16.bf16.f32 "
                 "{%0,%1,%2,%3}, {%4,%5,%6,%7}, {%8,%9}, {%0,%1,%2,%3};"
                 : "+f"(c[0]), "+f"(c[1]), "+f"(c[2]), "+f"(c[3])
                 : "r"(a[0]), "r"(a[1]), "r"(a[2]), "r"(a[3]), "r"(b0), "r"(b1));
}

// ---------------- prep kernels ----------------
__global__ void split_A(const float* __restrict__ X, __nv_bfloat16* __restrict__ out,
                        int M, int K) {
    int idx = blockIdx.x * blockDim.x + threadIdx.x;
    if (idx >= M * K) return;
    int m = idx / K, k = idx - m * K;
    float a = X[idx];
    __nv_bfloat16 a0 = __float2bfloat16(a);
    __nv_bfloat16 a1 = __float2bfloat16(a - __bfloat162float(a0));
    size_t base = (size_t)m * (2 * K);
    out[base + k] = a0;
    out[base + K + k] = a1;
}

__global__ void split_W_pair(const float* __restrict__ Wl, const float* __restrict__ Wr,
                             __nv_bfloat16* __restrict__ out, int K, int Nn) {
    int idx = blockIdx.x * blockDim.x + threadIdx.x;
    if (idx >= 2 * K * Nn) return;
    const float* W = (idx < K * Nn) ? Wl : Wr;
    int rem = (idx < K * Nn) ? idx : idx - K * Nn;
    int noff = (idx < K * Nn) ? 0 : Nn;
    int k = rem / Nn, n = rem - k * Nn;
    float b = W[rem];
    __nv_bfloat16 b0 = __float2bfloat16(b);
    __nv_bfloat16 b1 = __float2bfloat16(b - __bfloat162float(b0));
    size_t base = (size_t)(n + noff) * (3 * K);
    out[base + k] = b0;
    out[base + K + k] = b0;
    out[base + 2 * K + k] = b1;
}

__global__ void cat2(const float* __restrict__ a, const float* __restrict__ b,
                     float* __restrict__ o, int n) {
    int i = blockIdx.x * blockDim.x + threadIdx.x;
    if (i < n) { o[i] = a[i]; o[n + i] = b[i]; }
}

// ---------------- HMMA bf16 GEMM ----------------
// C = A'[M,KsA] (chunk-remapped to KsB) @ B''[Nn,KsB]^T + bias
// CTA tile 128x128, warp tile 32x64 (8 warps, 4x2), K-chunk 64, 3-stage cp.async.
// Output split: cols [0,Wn) -> Cl, [Wn,2Wn) -> Cr (compact, row stride Wn).
#define STAGE_BYTES 32768   // 16KB A + 16KB B

__global__ __launch_bounds__(256, 2)
void gemm_mma(const __nv_bfloat16* __restrict__ A, const __nv_bfloat16* __restrict__ B,
              const float* __restrict__ bias, float* __restrict__ Cl,
              float* __restrict__ Cr,
              int M, int KsA, int KsB, int Nn, int Wn) {
    extern __shared__ __align__(1024) char sm[];
    int tid = threadIdx.x;
    int wid = tid >> 5, lane = tid & 31;
    int m0 = blockIdx.y * 128, n0 = blockIdx.x * 128;
    int wm = wid >> 1, wn = wid & 1;     // warp tile: rows 32*wm, cols 64*wn
    uint32_t smb = smem_to_u32(sm);

    float acc[2][8][4];
#pragma unroll
    for (int t = 0; t < 2; t++)
#pragma unroll
        for (int j = 0; j < 8; j++)
#pragma unroll
            for (int q = 0; q < 4; q++) acc[t][j][q] = 0.f;

    int nch = KsB / 64;
    int nchA = KsA / 64;

    auto issue_load = [&](int c, int s) {
        uint32_t base = smb + s * STAGE_BYTES;
        int ca = (c < nchA) ? c : c - nchA;   // reuse a0 chunks for the b1 section
#pragma unroll
        for (int r = 0; r < 4; r++) {
            int idx = tid + r * 256;
            int row = idx >> 3, j = idx & 7;
            const __nv_bfloat16* gp = A + (size_t)(m0 + row) * KsA + ca * 64 + j * 8;
            uint32_t sa = base + SWZ128(row * 128 + j * 16);
            int sz = (m0 + row < M) ? 16 : 0;
            asm volatile("cp.async.cg.shared.global [%0], [%1], 16, %2;"
                         :: "r"(sa), "l"(gp), "r"(sz));
        }
#pragma unroll
        for (int r = 0; r < 4; r++) {
            int idx = tid + r * 256;
            int row = idx >> 3, j = idx & 7;
            const __nv_bfloat16* gp = B + (size_t)(n0 + row) * KsB + c * 64 + j * 8;
            uint32_t sa = base + 16384 + SWZ128(row * 128 + j * 16);
            asm volatile("cp.async.cg.shared.global [%0], [%1], 16;"
                         :: "r"(sa), "l"(gp));
        }
        asm volatile("cp.async.commit_group;");
    };

    issue_load(0, 0);
    if (nch > 1) issue_load(1, 1);

    for (int c = 0; c < nch; c++) {
        if (c + 1 < nch) asm volatile("cp.async.wait_group 1;");
        else             asm volatile("cp.async.wait_group 0;");
        __syncthreads();
        if (c + 2 < nch) issue_load(c + 2, (c + 2) % 3);

        uint32_t ab = smb + (c % 3) * STAGE_BYTES;
        uint32_t bb = ab + 16384;
#pragma unroll
        for (int kk = 0; kk < 4; kk++) {
            uint32_t af[2][4];
#pragma unroll
            for (int t = 0; t < 2; t++) {
                int rl = 32 * wm + 16 * t + (lane & 15);
                uint32_t ad = ab + SWZ128(rl * 128 + kk * 32 + (lane >> 4) * 16);
                ldmatrix_x4(af[t], ad);
            }
            uint32_t bf[4][4];
#pragma unroll
            for (int p = 0; p < 4; p++) {
                int nl = 64 * wn + 16 * p + ((lane >> 4) << 3) + (lane & 7);
                uint32_t bd = bb + SWZ128(nl * 128 + kk * 32 + ((lane >> 3) & 1) * 16);
                ldmatrix_x4(bf[p], bd);
            }
#pragma unroll
            for (int t = 0; t < 2; t++)
#pragma unroll
                for (int j = 0; j < 8; j++)
                    mma16816(acc[t][j], af[t],
                             bf[j >> 1][(j & 1) * 2], bf[j >> 1][(j & 1) * 2 + 1]);
        }
    }

    // epilogue: split into compact Cl / Cr (warp's 64-col block never straddles Wn)
    int cbase = n0 + 64 * wn;
    float* Cd = (cbase < Wn) ? Cl : Cr;
    int coff = (cbase < Wn) ? cbase : cbase - Wn;
#pragma unroll
    for (int t = 0; t < 2; t++) {
        int gr = m0 + 32 * wm + 16 * t + (lane >> 2);
#pragma unroll
        for (int j = 0; j < 8; j++) {
            int gc = coff + 8 * j + (lane & 3) * 2;
            float2 bi = *(const float2*)(bias + cbase + 8 * j + (lane & 3) * 2);
            if (gr < M) {
                float2 o = make_float2(acc[t][j][0] + bi.x, acc[t][j][1] + bi.y);
                *(float2*)(Cd + (size_t)gr * Wn + gc) = o;
            }
            if (gr + 8 < M) {
                float2 o = make_float2(acc[t][j][2] + bi.x, acc[t][j][3] + bi.y);
                *(float2*)(Cd + (size_t)(gr + 8) * Wn + gc) = o;
            }
        }
    }
}

// ---------------- BN prep ----------------
__global__ void bn_prep(const float* __restrict__ bias, const float* __restrict__ g,
                        const float* __restrict__ b, const float* __restrict__ m,
                        const float* __restrict__ v, float* __restrict__ s,
                        float* __restrict__ t, int n) {
    int i = blockIdx.x * blockDim.x + threadIdx.x;
    if (i < n) {
        float sc = g[i] * rsqrtf(v[i] + BN_EPS);
        s[i] = sc;
        t[i] = b[i] + (bias[i] - m[i]) * sc;
    }
}

// ---------------- CSR build ----------------
__global__ void deg_zero(int* deg) {
    int i = blockIdx.x * blockDim.x + threadIdx.x;
    if (i < N_NODES) deg[i] = 0;
}
__global__ void deg_hist(const int* __restrict__ ei, int* __restrict__ deg) {
    int i = blockIdx.x * blockDim.x + threadIdx.x;
    if (i >= ETOT) return;
    int dst = (i < N_EDGES) ? ei[N_EDGES + i] : (i - N_EDGES);
    atomicAdd(&deg[dst], 1);
}
__global__ void scan_kernel(const int* __restrict__ deg, int* __restrict__ off,
                            int* __restrict__ cursor) {
    __shared__ int warp_sums[32];
    const int T = 1024;
    int tid = threadIdx.x;
    int chunk = (N_NODES + T - 1) / T;
    int start = tid * chunk;
    int end = min(start + chunk, N_NODES);
    int local = 0;
    for (int i = start; i < end; i++) local += deg[i];
    int lane = tid & 31, wid = tid >> 5;
    int v = local;
#pragma unroll
    for (int o = 1; o < 32; o <<= 1) {
        int u = __shfl_up_sync(0xFFFFFFFFu, v, o);
        if (lane >= o) v += u;
    }
    if (lane == 31) warp_sums[wid] = v;
    __syncthreads();
    if (wid == 0) {
        int s = warp_sums[lane];
#pragma unroll
        for (int o = 1; o < 32; o <<= 1) {
            int u = __shfl_up_sync(0xFFFFFFFFu, s, o);
            if (lane >= o) s += u;
        }
        warp_sums[lane] = s;
    }
    __syncthreads();
    int excl = v - local + (wid > 0 ? warp_sums[wid - 1] : 0);
    int run = excl;
    for (int i = start; i < end; i++) {
        off[i] = run;
        cursor[i] = run;
        run += deg[i];
    }
    if (tid == T - 1) off[N_NODES] = run;
}
__global__ void csr_scatter(const int* __restrict__ ei, int* __restrict__ cursor,
                            int* __restrict__ csr_src) {
    int i = blockIdx.x * blockDim.x + threadIdx.x;
    if (i >= ETOT) return;
    int src, dst;
    if (i < N_EDGES) { src = ei[i]; dst = ei[N_EDGES + i]; }
    else             { src = dst = i - N_EDGES; }
    int pos = atomicAdd(&cursor[dst], 1);
    csr_src[pos] = src;
}

// ---------------- fused GATv2 aggregation (one warp per dst node) --------------
template<int H, bool OUTBF16>
__global__ __launch_bounds__(256)
void fused_agg(const float* __restrict__ xl, const float* __restrict__ xr,
               const float* __restrict__ att,
               const int* __restrict__ off, const int* __restrict__ csr_src,
               const float* __restrict__ bns, const float* __restrict__ bnt,
               void* __restrict__ outp) {
    int node = (blockIdx.x * blockDim.x + threadIdx.x) >> 5;
    int lane = threadIdx.x & 31;
    if (node >= N_NODES) return;
    const int Wd = H * 128;

    const float4* xr4 = (const float4*)(xr + (size_t)node * Wd);
    const float4* at4 = (const float4*)att;

    float4 xrr[H], attr[H], acc[H];
    float m[H], sum[H];
#pragma unroll
    for (int h = 0; h < H; h++) {
        xrr[h]  = xr4[h * 32 + lane];
        attr[h] = at4[h * 32 + lane];
        acc[h]  = make_float4(0.f, 0.f, 0.f, 0.f);
        m[h]    = -INFINITY;
        sum[h]  = 0.f;
    }

    int e0 = off[node], e1 = off[node + 1];
    int src = csr_src[e0];
    float4 v[H];
    {
        const float4* xs = (const float4*)(xl + (size_t)src * Wd);
#pragma unroll
        for (int h = 0; h < H; h++) v[h] = xs[h * 32 + lane];
    }

    for (int e = e0; e < e1; e++) {
        int nsrc = (e + 1 < e1) ? csr_src[e + 1] : src;
        const float4* xn = (const float4*)(xl + (size_t)nsrc * Wd);
        float4 vn[H];
#pragma unroll
        for (int h = 0; h < H; h++) vn[h] = xn[h * 32 + lane];

#pragma unroll
        for (int h = 0; h < H; h++) {
            float ex = v[h].x + xrr[h].x; ex = ex > 0.f ? ex : 0.2f * ex;
            float ey = v[h].y + xrr[h].y; ey = ey > 0.f ? ey : 0.2f * ey;
            float ez = v[h].z + xrr[h].z; ez = ez > 0.f ? ez : 0.2f * ez;
            float ew = v[h].w + xrr[h].w; ew = ew > 0.f ? ew : 0.2f * ew;
            float s = ex * attr[h].x + ey * attr[h].y + ez * attr[h].z + ew * attr[h].w;
#pragma unroll
            for (int o = 16; o > 0; o >>= 1) s += __shfl_xor_sync(0xFFFFFFFFu, s, o);

            float mn = fmaxf(m[h], s);
            float c  = __expf(m[h] - mn);
            float p  = __expf(s - mn);
            sum[h]   = sum[h] * c + p;
            acc[h].x = acc[h].x * c + p * v[h].x;
            acc[h].y = acc[h].y * c + p * v[h].y;
            acc[h].z = acc[h].z * c + p * v[h].z;
            acc[h].w = acc[h].w * c + p * v[h].w;
            m[h] = mn;
        }
#pragma unroll
        for (int h = 0; h < H; h++) v[h] = vn[h];
    }

#pragma unroll
    for (int h = 0; h < H; h++) {
        int cbase = h * 128 + lane * 4;
        float4 sc = *(const float4*)(bns + cbase);
        float4 tt = *(const float4*)(bnt + cbase);
        float inv = 1.f / sum[h];
        float4 o;
        o.x = fmaxf(fmaf(acc[h].x * inv, sc.x, tt.x), 0.f);
        o.y = fmaxf(fmaf(acc[h].y * inv, sc.y, tt.y), 0.f);
        o.z = fmaxf(fmaf(acc[h].z * inv, sc.z, tt.z), 0.f);
        o.w = fmaxf(fmaf(acc[h].w * inv, sc.w, tt.w), 0.f);
        if (OUTBF16) {
            __nv_bfloat16* out = (__nv_bfloat16*)outp;
            size_t base = (size_t)node * (2 * Wd);
            __nv_bfloat16 h0x = __float2bfloat16(o.x), h0y = __float2bfloat16(o.y);
            __nv_bfloat16 h0z = __float2bfloat16(o.z), h0w = __float2bfloat16(o.w);
            __nv_bfloat16 h1x = __float2bfloat16(o.x - __bfloat162float(h0x));
            __nv_bfloat16 h1y = __float2bfloat16(o.y - __bfloat162float(h0y));
            __nv_bfloat16 h1z = __float2bfloat16(o.z - __bfloat162float(h0z));
            __nv_bfloat16 h1w = __float2bfloat16(o.w - __bfloat162float(h0w));
            uint2 p0, p1;
            p0.x = ((uint32_t)__bfloat16_as_ushort(h0y) << 16) | __bfloat16_as_ushort(h0x);
            p0.y = ((uint32_t)__bfloat16_as_ushort(h0w) << 16) | __bfloat16_as_ushort(h0z);
            p1.x = ((uint32_t)__bfloat16_as_ushort(h1y) << 16) | __bfloat16_as_ushort(h1x);
            p1.y = ((uint32_t)__bfloat16_as_ushort(h1w) << 16) | __bfloat16_as_ushort(h1z);
            *(uint2*)(out + base + cbase) = p0;
            *(uint2*)(out + base + Wd + cbase) = p1;
        } else {
            float* out = (float*)outp;
            *(float4*)(out + (size_t)node * Wd + cbase) = o;
        }
    }
}

// ---------------- prediction head ----------------
__global__ void head_kernel(const float* __restrict__ z, const int* __restrict__ pe,
                            const float* __restrict__ pr, const float* __restrict__ pert,
                            const float* __restrict__ Wp, const float* __restrict__ bp,
                            float* __restrict__ out) {
    __shared__ float sw[(W2 * 2 + 3) * 2];
    for (int i = threadIdx.x; i < (W2 * 2 + 3) * 2; i += blockDim.x) sw[i] = Wp[i];
    __syncthreads();

    int w = (blockIdx.x * blockDim.x + threadIdx.x) >> 5;
    int lane = threadIdx.x & 31;
    if (w >= N_PRED) return;
    int s = pe[w], d = pe[N_PRED + w];
    const float4* zs = (const float4*)(z + (size_t)s * W2);
    const float4* zd = (const float4*)(z + (size_t)d * W2);

    float a0 = 0.f, a1 = 0.f;
#pragma unroll
    for (int q = 0; q < 2; q++) {
        int r = lane * 2 + q;
        float4 vz = zs[r];
        int base = (r * 4) * 2;
        a0 += vz.x * sw[base] + vz.y * sw[base + 2] + vz.z * sw[base + 4] + vz.w * sw[base + 6];
        a1 += vz.x * sw[base + 1] + vz.y * sw[base + 3] + vz.z * sw[base + 5] + vz.w * sw[base + 7];
        float4 vd = zd[r];
        int base2 = (W2 + r * 4) * 2;
        a0 += vd.x * sw[base2] + vd.y * sw[base2 + 2] + vd.z * sw[base2 + 4] + vd.w * sw[base2 + 6];
        a1 += vd.x * sw[base2 + 1] + vd.y * sw[base2 + 3] + vd.z * sw[base2 + 5] + vd.w * sw[base2 + 7];
    }
    if (lane == 0) {
        float prs = pr[s], prd = pr[d], pp = pert[s] * pert[d];
        int b0 = (2 * W2) * 2;
        a0 += prs * sw[b0] + prd * sw[b0 + 2] + pp * sw[b0 + 4];
        a1 += prs * sw[b0 + 1] + prd * sw[b0 + 3] + pp * sw[b0 + 5];
    }
#pragma unroll
    for (int o = 16; o > 0; o >>= 1) {
        a0 += __shfl_xor_sync(0xFFFFFFFFu, a0, o);
        a1 += __shfl_xor_sync(0xFFFFFFFFu, a1, o);
    }
    if (lane == 0) {
        out[(size_t)w * 2 + 0] = a0 + bp[0];
        out[(size_t)w * 2 + 1] = a1 + bp[1];
    }
}

// ---------------- launch ----------------
extern "C" void kernel_launch(void* const* d_in, const int* in_sizes, int n_in,
                              void* d_out, int out_size) {
    const float* x     = (const float*)d_in[0];
    const int*   ei    = (const int*)d_in[1];
    const int*   pe    = (const int*)d_in[2];
    const float* pert  = (const float*)d_in[3];
    const float* pr    = (const float*)d_in[4];
    const float* Wl1   = (const float*)d_in[5];
    const float* bl1   = (const float*)d_in[6];
    const float* Wr1   = (const float*)d_in[7];
    const float* br1   = (const float*)d_in[8];
    const float* att1  = (const float*)d_in[9];
    const float* bias1 = (const float*)d_in[10];
    const float* bn1g  = (const float*)d_in[11];
    const float* bn1b  = (const float*)d_in[12];
    const float* bn1m  = (const float*)d_in[13];
    const float* bn1v  = (const float*)d_in[14];
    const float* Wl2   = (const float*)d_in[15];
    const float* bl2   = (const float*)d_in[16];
    const float* Wr2   = (const float*)d_in[17];
    const float* br2   = (const float*)d_in[18];
    const float* att2  = (const float*)d_in[19];
    const float* bias2 = (const float*)d_in[20];
    const float* bn2g  = (const float*)d_in[21];
    const float* bn2b  = (const float*)d_in[22];
    const float* bn2m  = (const float*)d_in[23];
    const float* bn2v  = (const float*)d_in[24];
    const float* Wp    = (const float*)d_in[25];
    const float* bp    = (const float*)d_in[26];
    float* out = (float*)d_out;

    float *xl1, *xr1, *xl2, *xr2, *z, *bc1, *bc2;
    float *bns1, *bnt1, *bns2, *bnt2;
    int *deg, *off, *cursor, *csr_src;
    __nv_bfloat16 *As1, *As2, *Wc1s, *Wc2s;
    cudaGetSymbolAddress((void**)&xl1, g_xl1);
    cudaGetSymbolAddress((void**)&xr1, g_xr1);
    cudaGetSymbolAddress((void**)&xl2, g_xl2);
    cudaGetSymbolAddress((void**)&xr2, g_xr2);
    cudaGetSymbolAddress((void**)&z,  g_z);
    cudaGetSymbolAddress((void**)&bc1, g_bc1);
    cudaGetSymbolAddress((void**)&bc2, g_bc2);
    cudaGetSymbolAddress((void**)&bns1, g_bns1);
    cudaGetSymbolAddress((void**)&bnt1, g_bnt1);
    cudaGetSymbolAddress((void**)&bns2, g_bns2);
    cudaGetSymbolAddress((void**)&bnt2, g_bnt2);
    cudaGetSymbolAddress((void**)&deg, g_deg);
    cudaGetSymbolAddress((void**)&off, g_off);
    cudaGetSymbolAddress((void**)&cursor, g_cursor);
    cudaGetSymbolAddress((void**)&csr_src, g_csr_src);
    cudaGetSymbolAddress((void**)&As1, g_As1);
    cudaGetSymbolAddress((void**)&As2, g_As2);
    cudaGetSymbolAddress((void**)&Wc1s, g_Wc1s);
    cudaGetSymbolAddress((void**)&Wc2s, g_Wc2s);

    static int smem_cfg = 0;
    if (!smem_cfg) {
        cudaFuncSetAttribute(gemm_mma, cudaFuncAttributeMaxDynamicSharedMemorySize,
                             3 * STAGE_BYTES);
        smem_cfg = 1;
    }

    const int TB = 256;
    int mblk = (N_NODES + 127) / 128;              // 391
    int nwarp_blk = (N_NODES * 32 + TB - 1) / TB;

    // ---- layer-1 prep + GEMM (gemm is launch #4 for profiling) ----
    cat2<<<(W1 + 255) / 256, 256>>>(bl1, br1, bc1, W1);
    split_A<<<(N_NODES * K1 + TB - 1) / TB, TB>>>(x, As1, N_NODES, K1);
    split_W_pair<<<(2 * K1 * W1 + TB - 1) / TB, TB>>>(Wl1, Wr1, Wc1s, K1, W1);
    {
        dim3 g1((2 * W1) / 128, mblk);
        gemm_mma<<<g1, 256, 3 * STAGE_BYTES>>>(As1, Wc1s, bc1, xl1, xr1,
                                               N_NODES, 2 * K1, 3 * K1, 2 * W1, W1);
    }

    // ---- CSR build + BN folding + layer-2 prep ----
    deg_zero<<<(N_NODES + TB - 1) / TB, TB>>>(deg);
    deg_hist<<<(ETOT + TB - 1) / TB, TB>>>(ei, deg);
    scan_kernel<<<1, 1024>>>(deg, off, cursor);
    csr_scatter<<<(ETOT + TB - 1) / TB, TB>>>(ei, cursor, csr_src);
    bn_prep<<<(W1 + 255) / 256, 256>>>(bias1, bn1g, bn1b, bn1m, bn1v, bns1, bnt1, W1);
    bn_prep<<<(W2 + 255) / 256, 256>>>(bias2, bn2g, bn2b, bn2m, bn2v, bns2, bnt2, W2);
    cat2<<<(W2 + 255) / 256, 256>>>(bl2, br2, bc2, W2);
    split_W_pair<<<(2 * K2 * W2 + TB - 1) / TB, TB>>>(Wl2, Wr2, Wc2s, K2, W2);

    // ---- layer-1 aggregation -> bf16 [a0|a1] for layer-2 GEMM ----
    fused_agg<H1, true><<<nwarp_blk, TB>>>(xl1, xr1, att1,
                                           off, csr_src, bns1, bnt1, As2);

    // ---- layer 2 ----
    {
        dim3 g2((2 * W2) / 128, mblk);
        gemm_mma<<<g2, 256, 3 * STAGE_BYTES>>>(As2, Wc2s, bc2, xl2, xr2,
                                               N_NODES, 2 * K2, 3 * K2, 2 * W2, W2);
    }
    fused_agg<H2, false><<<nwarp_blk, TB>>>(xl2, xr2, att2,
                                            off, csr_src, bns2, bnt2, z);

    // ---- head ----
    head_kernel<<<(N_PRED * 32 + TB - 1) / TB, TB>>>(z, pe, pr, pert, Wp, bp, out);
}

// round 9
// speedup vs baseline: 1.0811x; 1.0385x over previous
#include <cuda_runtime.h>
#include <cuda_bf16.h>
#include <math.h>
#include <cstdint>

// ---------------- problem constants ----------------
#define N_NODES 50000
#define N_EDGES 600000
#define N_PRED  200000
#define ETOT    (N_EDGES + N_NODES)
#define W1      512
#define W2      256
#define H1      4
#define H2      2
#define K1      128
#define K2      512
#define BN_EPS  1e-5f

// ---------------- scratch (device globals) ----------------
__device__ float g_xl1[(size_t)N_NODES * W1];
__device__ float g_xr1[(size_t)N_NODES * W1];
__device__ float g_xl2[(size_t)N_NODES * W2];
__device__ float g_xr2[(size_t)N_NODES * W2];
__device__ float g_z  [(size_t)N_NODES * W2];

__device__ __nv_bfloat16 g_As1[(size_t)N_NODES * (2 * K1)];   // [a0|a1]
__device__ __nv_bfloat16 g_As2[(size_t)N_NODES * (2 * K2)];   // [a0|a1]
__device__ __nv_bfloat16 g_Wc1s[(2 * W1) * (3 * K1)];         // rows [Wl|Wr], cols [b0|b0|b1]
__device__ __nv_bfloat16 g_Wc2s[(2 * W2) * (3 * K2)];

__device__ float g_bc1[2 * W1];
__device__ float g_bc2[2 * W2];

__device__ int g_deg[N_NODES];
__device__ int g_off[N_NODES + 1];
__device__ int g_cursor[N_NODES];
__device__ int g_csr_src[ETOT];

__device__ float g_bns1[W1];
__device__ float g_bnt1[W1];
__device__ float g_bns2[W2];
__device__ float g_bnt2[W2];

// ---------------- helpers ----------------
__device__ __forceinline__ uint32_t smem_to_u32(const void* p) {
    uint32_t a;
    asm("{ .reg .u64 t; cvta.to.shared.u64 t, %1; cvt.u32.u64 %0, t; }" : "=r"(a) : "l"(p));
    return a;
}
#define SWZ128(b) ((b) ^ (((b) >> 3) & 0x70))

__device__ __forceinline__ void ldmatrix_x4(uint32_t* r, uint32_t addr) {
    asm volatile("ldmatrix.sync.aligned.m8n8.x4.shared.b16 {%0,%1,%2,%3}, [%4];"
                 : "=r"(r[0]), "=r"(r[1]), "=r"(r[2]), "=r"(r[3]) : "r"(addr));
}
__device__ __forceinline__ void mma16816(float* c, const uint32_t* a,
                                         uint32_t b0, uint32_t b1) {
    asm volatile("mma.sync.aligned.m16n8k16.row.col.f32.bf16.bf16.f32 "
                 "{%0,%1,%2,%3}, {%4,%5,%6,%7}, {%8,%9}, {%0,%1,%2,%3};"
                 : "+f"(c[0]), "+f"(c[1]), "+f"(c[2]), "+f"(c[3])
                 : "r"(a[0]), "r"(a[1]), "r"(a[2]), "r"(a[3]), "r"(b0), "r"(b1));
}

// ---------------- prep kernels ----------------
__global__ void split_A(const float* __restrict__ X, __nv_bfloat16* __restrict__ out,
                        int M, int K) {
    int idx = blockIdx.x * blockDim.x + threadIdx.x;
    if (idx >= M * K) return;
    int m = idx / K, k = idx - m * K;
    float a = X[idx];
    __nv_bfloat16 a0 = __float2bfloat16(a);
    __nv_bfloat16 a1 = __float2bfloat16(a - __bfloat162float(a0));
    size_t base = (size_t)m * (2 * K);
    out[base + k] = a0;
    out[base + K + k] = a1;
}

__global__ void split_W_pair(const float* __restrict__ Wl, const float* __restrict__ Wr,
                             __nv_bfloat16* __restrict__ out, int K, int Nn) {
    int idx = blockIdx.x * blockDim.x + threadIdx.x;
    if (idx >= 2 * K * Nn) return;
    const float* W = (idx < K * Nn) ? Wl : Wr;
    int rem = (idx < K * Nn) ? idx : idx - K * Nn;
    int noff = (idx < K * Nn) ? 0 : Nn;
    int k = rem / Nn, n = rem - k * Nn;
    float b = W[rem];
    __nv_bfloat16 b0 = __float2bfloat16(b);
    __nv_bfloat16 b1 = __float2bfloat16(b - __bfloat162float(b0));
    size_t base = (size_t)(n + noff) * (3 * K);
    out[base + k] = b0;
    out[base + K + k] = b0;
    out[base + 2 * K + k] = b1;
}

__global__ void cat2(const float* __restrict__ a, const float* __restrict__ b,
                     float* __restrict__ o, int n) {
    int i = blockIdx.x * blockDim.x + threadIdx.x;
    if (i < n) { o[i] = a[i]; o[n + i] = b[i]; }
}

// ---------------- HMMA bf16 GEMM ----------------
// CTA tile 128x128, warp tile 32x64 (8 warps, 4x2), K-chunk 64, 3-stage cp.async.
#define STAGE_BYTES 32768   // 16KB A + 16KB B

__global__ __launch_bounds__(256, 2)
void gemm_mma(const __nv_bfloat16* __restrict__ A, const __nv_bfloat16* __restrict__ B,
              const float* __restrict__ bias, float* __restrict__ Cl,
              float* __restrict__ Cr,
              int M, int KsA, int KsB, int Nn, int Wn) {
    extern __shared__ __align__(1024) char sm[];
    int tid = threadIdx.x;
    int wid = tid >> 5, lane = tid & 31;
    int m0 = blockIdx.y * 128, n0 = blockIdx.x * 128;
    int wm = wid >> 1, wn = wid & 1;
    uint32_t smb = smem_to_u32(sm);

    float acc[2][8][4];
#pragma unroll
    for (int t = 0; t < 2; t++)
#pragma unroll
        for (int j = 0; j < 8; j++)
#pragma unroll
            for (int q = 0; q < 4; q++) acc[t][j][q] = 0.f;

    int nch = KsB / 64;
    int nchA = KsA / 64;

    auto issue_load = [&](int c, int s) {
        uint32_t base = smb + s * STAGE_BYTES;
        int ca = (c < nchA) ? c : c - nchA;   // reuse a0 chunks for the b1 section
#pragma unroll
        for (int r = 0; r < 4; r++) {
            int idx = tid + r * 256;
            int row = idx >> 3, j = idx & 7;
            const __nv_bfloat16* gp = A + (size_t)(m0 + row) * KsA + ca * 64 + j * 8;
            uint32_t sa = base + SWZ128(row * 128 + j * 16);
            int sz = (m0 + row < M) ? 16 : 0;
            asm volatile("cp.async.cg.shared.global [%0], [%1], 16, %2;"
                         :: "r"(sa), "l"(gp), "r"(sz));
        }
#pragma unroll
        for (int r = 0; r < 4; r++) {
            int idx = tid + r * 256;
            int row = idx >> 3, j = idx & 7;
            const __nv_bfloat16* gp = B + (size_t)(n0 + row) * KsB + c * 64 + j * 8;
            uint32_t sa = base + 16384 + SWZ128(row * 128 + j * 16);
            asm volatile("cp.async.cg.shared.global [%0], [%1], 16;"
                         :: "r"(sa), "l"(gp));
        }
        asm volatile("cp.async.commit_group;");
    };

    issue_load(0, 0);
    if (nch > 1) issue_load(1, 1);

    for (int c = 0; c < nch; c++) {
        if (c + 1 < nch) asm volatile("cp.async.wait_group 1;");
        else             asm volatile("cp.async.wait_group 0;");
        __syncthreads();
        if (c + 2 < nch) issue_load(c + 2, (c + 2) % 3);

        uint32_t ab = smb + (c % 3) * STAGE_BYTES;
        uint32_t bb = ab + 16384;
#pragma unroll
        for (int kk = 0; kk < 4; kk++) {
            uint32_t af[2][4];
#pragma unroll
            for (int t = 0; t < 2; t++) {
                int rl = 32 * wm + 16 * t + (lane & 15);
                uint32_t ad = ab + SWZ128(rl * 128 + kk * 32 + (lane >> 4) * 16);
                ldmatrix_x4(af[t], ad);
            }
            uint32_t bf[4][4];
#pragma unroll
            for (int p = 0; p < 4; p++) {
                int nl = 64 * wn + 16 * p + ((lane >> 4) << 3) + (lane & 7);
                uint32_t bd = bb + SWZ128(nl * 128 + kk * 32 + ((lane >> 3) & 1) * 16);
                ldmatrix_x4(bf[p], bd);
            }
#pragma unroll
            for (int t = 0; t < 2; t++)
#pragma unroll
                for (int j = 0; j < 8; j++)
                    mma16816(acc[t][j], af[t],
                             bf[j >> 1][(j & 1) * 2], bf[j >> 1][(j & 1) * 2 + 1]);
        }
    }

    // epilogue: split into compact Cl / Cr
    int cbase = n0 + 64 * wn;
    float* Cd = (cbase < Wn) ? Cl : Cr;
    int coff = (cbase < Wn) ? cbase : cbase - Wn;
#pragma unroll
    for (int t = 0; t < 2; t++) {
        int gr = m0 + 32 * wm + 16 * t + (lane >> 2);
#pragma unroll
        for (int j = 0; j < 8; j++) {
            int gc = coff + 8 * j + (lane & 3) * 2;
            float2 bi = *(const float2*)(bias + cbase + 8 * j + (lane & 3) * 2);
            if (gr < M) {
                float2 o = make_float2(acc[t][j][0] + bi.x, acc[t][j][1] + bi.y);
                *(float2*)(Cd + (size_t)gr * Wn + gc) = o;
            }
            if (gr + 8 < M) {
                float2 o = make_float2(acc[t][j][2] + bi.x, acc[t][j][3] + bi.y);
                *(float2*)(Cd + (size_t)(gr + 8) * Wn + gc) = o;
            }
        }
    }
}

// ---------------- BN prep ----------------
__global__ void bn_prep(const float* __restrict__ bias, const float* __restrict__ g,
                        const float* __restrict__ b, const float* __restrict__ m,
                        const float* __restrict__ v, float* __restrict__ s,
                        float* __restrict__ t, int n) {
    int i = blockIdx.x * blockDim.x + threadIdx.x;
    if (i < n) {
        float sc = g[i] * rsqrtf(v[i] + BN_EPS);
        s[i] = sc;
        t[i] = b[i] + (bias[i] - m[i]) * sc;
    }
}

// ---------------- CSR build ----------------
__global__ void deg_zero(int* deg) {
    int i = blockIdx.x * blockDim.x + threadIdx.x;
    if (i < N_NODES) deg[i] = 0;
}
__global__ void deg_hist(const int* __restrict__ ei, int* __restrict__ deg) {
    int i = blockIdx.x * blockDim.x + threadIdx.x;
    if (i >= ETOT) return;
    int dst = (i < N_EDGES) ? ei[N_EDGES + i] : (i - N_EDGES);
    atomicAdd(&deg[dst], 1);
}
__global__ void scan_kernel(const int* __restrict__ deg, int* __restrict__ off,
                            int* __restrict__ cursor) {
    __shared__ int warp_sums[32];
    const int T = 1024;
    int tid = threadIdx.x;
    int chunk = (N_NODES + T - 1) / T;
    int start = tid * chunk;
    int end = min(start + chunk, N_NODES);
    int local = 0;
    for (int i = start; i < end; i++) local += deg[i];
    int lane = tid & 31, wid = tid >> 5;
    int v = local;
#pragma unroll
    for (int o = 1; o < 32; o <<= 1) {
        int u = __shfl_up_sync(0xFFFFFFFFu, v, o);
        if (lane >= o) v += u;
    }
    if (lane == 31) warp_sums[wid] = v;
    __syncthreads();
    if (wid == 0) {
        int s = warp_sums[lane];
#pragma unroll
        for (int o = 1; o < 32; o <<= 1) {
            int u = __shfl_up_sync(0xFFFFFFFFu, s, o);
            if (lane >= o) s += u;
        }
        warp_sums[lane] = s;
    }
    __syncthreads();
    int excl = v - local + (wid > 0 ? warp_sums[wid - 1] : 0);
    int run = excl;
    for (int i = start; i < end; i++) {
        off[i] = run;
        cursor[i] = run;
        run += deg[i];
    }
    if (tid == T - 1) off[N_NODES] = run;
}
__global__ void csr_scatter(const int* __restrict__ ei, int* __restrict__ cursor,
                            int* __restrict__ csr_src) {
    int i = blockIdx.x * blockDim.x + threadIdx.x;
    if (i >= ETOT) return;
    int src, dst;
    if (i < N_EDGES) { src = ei[i]; dst = ei[N_EDGES + i]; }
    else             { src = dst = i - N_EDGES; }
    int pos = atomicAdd(&cursor[dst], 1);
    csr_src[pos] = src;
}

// ---------------- fused GATv2 aggregation (one warp per dst node) --------------
template<int H, bool OUTBF16>
__global__ __launch_bounds__(256)
void fused_agg(const float* __restrict__ xl, const float* __restrict__ xr,
               const float* __restrict__ att,
               const int* __restrict__ off, const int* __restrict__ csr_src,
               const float* __restrict__ bns, const float* __restrict__ bnt,
               void* __restrict__ outp) {
    int node = (blockIdx.x * blockDim.x + threadIdx.x) >> 5;
    int lane = threadIdx.x & 31;
    if (node >= N_NODES) return;
    const int Wd = H * 128;

    const float4* xr4 = (const float4*)(xr + (size_t)node * Wd);
    const float4* at4 = (const float4*)att;

    float4 xrr[H], attr[H], acc[H];
    float m[H], sum[H];
#pragma unroll
    for (int h = 0; h < H; h++) {
        xrr[h]  = xr4[h * 32 + lane];
        attr[h] = at4[h * 32 + lane];
        acc[h]  = make_float4(0.f, 0.f, 0.f, 0.f);
        m[h]    = -INFINITY;
        sum[h]  = 0.f;
    }

    int e0 = off[node], e1 = off[node + 1];
    int src = csr_src[e0];
    float4 v[H];
    {
        const float4* xs = (const float4*)(xl + (size_t)src * Wd);
#pragma unroll
        for (int h = 0; h < H; h++) v[h] = xs[h * 32 + lane];
    }

    for (int e = e0; e < e1; e++) {
        int nsrc = (e + 1 < e1) ? csr_src[e + 1] : src;
        const float4* xn = (const float4*)(xl + (size_t)nsrc * Wd);
        float4 vn[H];
#pragma unroll
        for (int h = 0; h < H; h++) vn[h] = xn[h * 32 + lane];

#pragma unroll
        for (int h = 0; h < H; h++) {
            float ex = v[h].x + xrr[h].x; ex = ex > 0.f ? ex : 0.2f * ex;
            float ey = v[h].y + xrr[h].y; ey = ey > 0.f ? ey : 0.2f * ey;
            float ez = v[h].z + xrr[h].z; ez = ez > 0.f ? ez : 0.2f * ez;
            float ew = v[h].w + xrr[h].w; ew = ew > 0.f ? ew : 0.2f * ew;
            float s = ex * attr[h].x + ey * attr[h].y + ez * attr[h].z + ew * attr[h].w;
#pragma unroll
            for (int o = 16; o > 0; o >>= 1) s += __shfl_xor_sync(0xFFFFFFFFu, s, o);

            float mn = fmaxf(m[h], s);
            float c  = __expf(m[h] - mn);
            float p  = __expf(s - mn);
            sum[h]   = sum[h] * c + p;
            acc[h].x = acc[h].x * c + p * v[h].x;
            acc[h].y = acc[h].y * c + p * v[h].y;
            acc[h].z = acc[h].z * c + p * v[h].z;
            acc[h].w = acc[h].w * c + p * v[h].w;
            m[h] = mn;
        }
#pragma unroll
        for (int h = 0; h < H; h++) v[h] = vn[h];
    }

#pragma unroll
    for (int h = 0; h < H; h++) {
        int cbase = h * 128 + lane * 4;
        float4 sc = *(const float4*)(bns + cbase);
        float4 tt = *(const float4*)(bnt + cbase);
        float inv = 1.f / sum[h];
        float4 o;
        o.x = fmaxf(fmaf(acc[h].x * inv, sc.x, tt.x), 0.f);
        o.y = fmaxf(fmaf(acc[h].y * inv, sc.y, tt.y), 0.f);
        o.z = fmaxf(fmaf(acc[h].z * inv, sc.z, tt.z), 0.f);
        o.w = fmaxf(fmaf(acc[h].w * inv, sc.w, tt.w), 0.f);
        if (OUTBF16) {
            __nv_bfloat16* out = (__nv_bfloat16*)outp;
            size_t base = (size_t)node * (2 * Wd);
            __nv_bfloat16 h0x = __float2bfloat16(o.x), h0y = __float2bfloat16(o.y);
            __nv_bfloat16 h0z = __float2bfloat16(o.z), h0w = __float2bfloat16(o.w);
            __nv_bfloat16 h1x = __float2bfloat16(o.x - __bfloat162float(h0x));
            __nv_bfloat16 h1y = __float2bfloat16(o.y - __bfloat162float(h0y));
            __nv_bfloat16 h1z = __float2bfloat16(o.z - __bfloat162float(h0z));
            __nv_bfloat16 h1w = __float2bfloat16(o.w - __bfloat162float(h0w));
            uint2 p0, p1;
            p0.x = ((uint32_t)__bfloat16_as_ushort(h0y) << 16) | __bfloat16_as_ushort(h0x);
            p0.y = ((uint32_t)__bfloat16_as_ushort(h0w) << 16) | __bfloat16_as_ushort(h0z);
            p1.x = ((uint32_t)__bfloat16_as_ushort(h1y) << 16) | __bfloat16_as_ushort(h1x);
            p1.y = ((uint32_t)__bfloat16_as_ushort(h1w) << 16) | __bfloat16_as_ushort(h1z);
            *(uint2*)(out + base + cbase) = p0;
            *(uint2*)(out + base + Wd + cbase) = p1;
        } else {
            float* out = (float*)outp;
            *(float4*)(out + (size_t)node * Wd + cbase) = o;
        }
    }
}

// ---------------- prediction head ----------------
__global__ void head_kernel(const float* __restrict__ z, const int* __restrict__ pe,
                            const float* __restrict__ pr, const float* __restrict__ pert,
                            const float* __restrict__ Wp, const float* __restrict__ bp,
                            float* __restrict__ out) {
    __shared__ float sw[(W2 * 2 + 3) * 2];
    for (int i = threadIdx.x; i < (W2 * 2 + 3) * 2; i += blockDim.x) sw[i] = Wp[i];
    __syncthreads();

    int w = (blockIdx.x * blockDim.x + threadIdx.x) >> 5;
    int lane = threadIdx.x & 31;
    if (w >= N_PRED) return;
    int s = pe[w], d = pe[N_PRED + w];
    const float4* zs = (const float4*)(z + (size_t)s * W2);
    const float4* zd = (const float4*)(z + (size_t)d * W2);

    float a0 = 0.f, a1 = 0.f;
#pragma unroll
    for (int q = 0; q < 2; q++) {
        int r = lane * 2 + q;
        float4 vz = zs[r];
        int base = (r * 4) * 2;
        a0 += vz.x * sw[base] + vz.y * sw[base + 2] + vz.z * sw[base + 4] + vz.w * sw[base + 6];
        a1 += vz.x * sw[base + 1] + vz.y * sw[base + 3] + vz.z * sw[base + 5] + vz.w * sw[base + 7];
        float4 vd = zd[r];
        int base2 = (W2 + r * 4) * 2;
        a0 += vd.x * sw[base2] + vd.y * sw[base2 + 2] + vd.z * sw[base2 + 4] + vd.w * sw[base2 + 6];
        a1 += vd.x * sw[base2 + 1] + vd.y * sw[base2 + 3] + vd.z * sw[base2 + 5] + vd.w * sw[base2 + 7];
    }
    if (lane == 0) {
        float prs = pr[s], prd = pr[d], pp = pert[s] * pert[d];
        int b0 = (2 * W2) * 2;
        a0 += prs * sw[b0] + prd * sw[b0 + 2] + pp * sw[b0 + 4];
        a1 += prs * sw[b0 + 1] + prd * sw[b0 + 3] + pp * sw[b0 + 5];
    }
#pragma unroll
    for (int o = 16; o > 0; o >>= 1) {
        a0 += __shfl_xor_sync(0xFFFFFFFFu, a0, o);
        a1 += __shfl_xor_sync(0xFFFFFFFFu, a1, o);
    }
    if (lane == 0) {
        out[(size_t)w * 2 + 0] = a0 + bp[0];
        out[(size_t)w * 2 + 1] = a1 + bp[1];
    }
}

// ---------------- launch ----------------
extern "C" void kernel_launch(void* const* d_in, const int* in_sizes, int n_in,
                              void* d_out, int out_size) {
    const float* x     = (const float*)d_in[0];
    const int*   ei    = (const int*)d_in[1];
    const int*   pe    = (const int*)d_in[2];
    const float* pert  = (const float*)d_in[3];
    const float* pr    = (const float*)d_in[4];
    const float* Wl1   = (const float*)d_in[5];
    const float* bl1   = (const float*)d_in[6];
    const float* Wr1   = (const float*)d_in[7];
    const float* br1   = (const float*)d_in[8];
    const float* att1  = (const float*)d_in[9];
    const float* bias1 = (const float*)d_in[10];
    const float* bn1g  = (const float*)d_in[11];
    const float* bn1b  = (const float*)d_in[12];
    const float* bn1m  = (const float*)d_in[13];
    const float* bn1v  = (const float*)d_in[14];
    const float* Wl2   = (const float*)d_in[15];
    const float* bl2   = (const float*)d_in[16];
    const float* Wr2   = (const float*)d_in[17];
    const float* br2   = (const float*)d_in[18];
    const float* att2  = (const float*)d_in[19];
    const float* bias2 = (const float*)d_in[20];
    const float* bn2g  = (const float*)d_in[21];
    const float* bn2b  = (const float*)d_in[22];
    const float* bn2m  = (const float*)d_in[23];
    const float* bn2v  = (const float*)d_in[24];
    const float* Wp    = (const float*)d_in[25];
    const float* bp    = (const float*)d_in[26];
    float* out = (float*)d_out;

    float *xl1, *xr1, *xl2, *xr2, *z, *bc1, *bc2;
    float *bns1, *bnt1, *bns2, *bnt2;
    int *deg, *off, *cursor, *csr_src;
    __nv_bfloat16 *As1, *As2, *Wc1s, *Wc2s;
    cudaGetSymbolAddress((void**)&xl1, g_xl1);
    cudaGetSymbolAddress((void**)&xr1, g_xr1);
    cudaGetSymbolAddress((void**)&xl2, g_xl2);
    cudaGetSymbolAddress((void**)&xr2, g_xr2);
    cudaGetSymbolAddress((void**)&z,  g_z);
    cudaGetSymbolAddress((void**)&bc1, g_bc1);
    cudaGetSymbolAddress((void**)&bc2, g_bc2);
    cudaGetSymbolAddress((void**)&bns1, g_bns1);
    cudaGetSymbolAddress((void**)&bnt1, g_bnt1);
    cudaGetSymbolAddress((void**)&bns2, g_bns2);
    cudaGetSymbolAddress((void**)&bnt2, g_bnt2);
    cudaGetSymbolAddress((void**)&deg, g_deg);
    cudaGetSymbolAddress((void**)&off, g_off);
    cudaGetSymbolAddress((void**)&cursor, g_cursor);
    cudaGetSymbolAddress((void**)&csr_src, g_csr_src);
    cudaGetSymbolAddress((void**)&As1, g_As1);
    cudaGetSymbolAddress((void**)&As2, g_As2);
    cudaGetSymbolAddress((void**)&Wc1s, g_Wc1s);
    cudaGetSymbolAddress((void**)&Wc2s, g_Wc2s);

    static int s_init = 0;
    static cudaStream_t s_side;
    static cudaEvent_t s_evF, s_evJ;
    if (!s_init) {
        cudaFuncSetAttribute(gemm_mma, cudaFuncAttributeMaxDynamicSharedMemorySize,
                             3 * STAGE_BYTES);
        cudaStreamCreateWithFlags(&s_side, cudaStreamNonBlocking);
        cudaEventCreateWithFlags(&s_evF, cudaEventDisableTiming);
        cudaEventCreateWithFlags(&s_evJ, cudaEventDisableTiming);
        s_init = 1;
    }

    const int TB = 256;
    int mblk = (N_NODES + 127) / 128;              // 391
    int nwarp_blk = (N_NODES * 32 + TB - 1) / TB;

    // ---- fork: side stream runs CSR + BN folding + layer-2 prep under GEMM1 ----
    cudaEventRecord(s_evF, 0);
    cudaStreamWaitEvent(s_side, s_evF, 0);

    deg_zero<<<(N_NODES + TB - 1) / TB, TB, 0, s_side>>>(deg);
    deg_hist<<<(ETOT + TB - 1) / TB, TB, 0, s_side>>>(ei, deg);
    scan_kernel<<<1, 1024, 0, s_side>>>(deg, off, cursor);
    csr_scatter<<<(ETOT + TB - 1) / TB, TB, 0, s_side>>>(ei, cursor, csr_src);
    bn_prep<<<(W1 + 255) / 256, 256, 0, s_side>>>(bias1, bn1g, bn1b, bn1m, bn1v,
                                                  bns1, bnt1, W1);
    bn_prep<<<(W2 + 255) / 256, 256, 0, s_side>>>(bias2, bn2g, bn2b, bn2m, bn2v,
                                                  bns2, bnt2, W2);
    cat2<<<(W2 + 255) / 256, 256, 0, s_side>>>(bl2, br2, bc2, W2);
    split_W_pair<<<(2 * K2 * W2 + TB - 1) / TB, TB, 0, s_side>>>(Wl2, Wr2, Wc2s, K2, W2);
    cudaEventRecord(s_evJ, s_side);

    // ---- main: layer-1 prep + GEMM1 ----
    cat2<<<(W1 + 255) / 256, 256>>>(bl1, br1, bc1, W1);
    split_A<<<(N_NODES * K1 + TB - 1) / TB, TB>>>(x, As1, N_NODES, K1);
    split_W_pair<<<(2 * K1 * W1 + TB - 1) / TB, TB>>>(Wl1, Wr1, Wc1s, K1, W1);
    {
        dim3 g1((2 * W1) / 128, mblk);
        gemm_mma<<<g1, 256, 3 * STAGE_BYTES>>>(As1, Wc1s, bc1, xl1, xr1,
                                               N_NODES, 2 * K1, 3 * K1, 2 * W1, W1);
    }

    // ---- join before aggregation (needs CSR + bns1; GEMM2 needs Wc2s/bc2) ----
    cudaStreamWaitEvent(0, s_evJ, 0);

    // ---- layer-1 aggregation -> bf16 [a0|a1] for layer-2 GEMM ----
    fused_agg<H1, true><<<nwarp_blk, TB>>>(xl1, xr1, att1,
                                           off, csr_src, bns1, bnt1, As2);

    // ---- layer 2 ----
    {
        dim3 g2((2 * W2) / 128, mblk);
        gemm_mma<<<g2, 256, 3 * STAGE_BYTES>>>(As2, Wc2s, bc2, xl2, xr2,
                                               N_NODES, 2 * K2, 3 * K2, 2 * W2, W2);
    }
    fused_agg<H2, false><<<nwarp_blk, TB>>>(xl2, xr2, att2,
                                            off, csr_src, bns2, bnt2, z);

    // ---- head ----
    head_kernel<<<(N_PRED * 32 + TB - 1) / TB, TB>>>(z, pe, pr, pert, Wp, bp, out);
}

// round 10
// speedup vs baseline: 1.1101x; 1.0268x over previous
#include <cuda_runtime.h>
#include <cuda_bf16.h>
#include <math.h>
#include <cstdint>

// ---------------- problem constants ----------------
#define N_NODES 50000
#define N_EDGES 600000
#define N_PRED  200000
#define ETOT    (N_EDGES + N_NODES)
#define W1      512
#define W2      256
#define H1      4
#define H2      2
#define K1      128
#define K2      512
#define BN_EPS  1e-5f
#define NCHUNK  4

// ---------------- scratch (device globals) ----------------
__device__ float g_xl1[(size_t)N_NODES * W1];
__device__ float g_xr1[(size_t)N_NODES * W1];
__device__ float g_xl2[(size_t)N_NODES * W2];
__device__ float g_xr2[(size_t)N_NODES * W2];
__device__ float g_z  [(size_t)N_NODES * W2];

__device__ __nv_bfloat16 g_As1[(size_t)N_NODES * (2 * K1)];   // [a0|a1]
__device__ __nv_bfloat16 g_As2[(size_t)N_NODES * (2 * K2)];   // [a0|a1]
__device__ __nv_bfloat16 g_Wc1s[(2 * W1) * (3 * K1)];         // rows [Wl|Wr], cols [b0|b0|b1]
__device__ __nv_bfloat16 g_Wc2s[(2 * W2) * (3 * K2)];

__device__ float g_bc1[2 * W1];
__device__ float g_bc2[2 * W2];

__device__ int g_deg[N_NODES];
__device__ int g_off[N_NODES + 1];
__device__ int g_cursor[N_NODES];
__device__ int g_csr_src[ETOT];

__device__ float g_bns1[W1];
__device__ float g_bnt1[W1];
__device__ float g_bns2[W2];
__device__ float g_bnt2[W2];

// ---------------- helpers ----------------
__device__ __forceinline__ uint32_t smem_to_u32(const void* p) {
    uint32_t a;
    asm("{ .reg .u64 t; cvta.to.shared.u64 t, %1; cvt.u32.u64 %0, t; }" : "=r"(a) : "l"(p));
    return a;
}
#define SWZ128(b) ((b) ^ (((b) >> 3) & 0x70))

__device__ __forceinline__ void ldmatrix_x4(uint32_t* r, uint32_t addr) {
    asm volatile("ldmatrix.sync.aligned.m8n8.x4.shared.b16 {%0,%1,%2,%3}, [%4];"
                 : "=r"(r[0]), "=r"(r[1]), "=r"(r[2]), "=r"(r[3]) : "r"(addr));
}
__device__ __forceinline__ void mma16816(float* c, const uint32_t* a,
                                         uint32_t b0, uint32_t b1) {
    asm volatile("mma.sync.aligned.m16n8k16.row.col.f32.bf16.bf16.f32 "
                 "{%0,%1,%2,%3}, {%4,%5,%6,%7}, {%8,%9}, {%0,%1,%2,%3};"
                 : "+f"(c[0]), "+f"(c[1]), "+f"(c[2]), "+f"(c[3])
                 : "r"(a[0]), "r"(a[1]), "r"(a[2]), "r"(a[3]), "r"(b0), "r"(b1));
}

// ---------------- prep kernels ----------------
__global__ void split_A(const float* __restrict__ X, __nv_bfloat16* __restrict__ out,
                        int M, int K) {
    int idx = blockIdx.x * blockDim.x + threadIdx.x;
    if (idx >= M * K) return;
    int m = idx / K, k = idx - m * K;
    float a = X[idx];
    __nv_bfloat16 a0 = __float2bfloat16(a);
    __nv_bfloat16 a1 = __float2bfloat16(a - __bfloat162float(a0));
    size_t base = (size_t)m * (2 * K);
    out[base + k] = a0;
    out[base + K + k] = a1;
}

__global__ void split_W_pair(const float* __restrict__ Wl, const float* __restrict__ Wr,
                             __nv_bfloat16* __restrict__ out, int K, int Nn) {
    int idx = blockIdx.x * blockDim.x + threadIdx.x;
    if (idx >= 2 * K * Nn) return;
    const float* W = (idx < K * Nn) ? Wl : Wr;
    int rem = (idx < K * Nn) ? idx : idx - K * Nn;
    int noff = (idx < K * Nn) ? 0 : Nn;
    int k = rem / Nn, n = rem - k * Nn;
    float b = W[rem];
    __nv_bfloat16 b0 = __float2bfloat16(b);
    __nv_bfloat16 b1 = __float2bfloat16(b - __bfloat162float(b0));
    size_t base = (size_t)(n + noff) * (3 * K);
    out[base + k] = b0;
    out[base + K + k] = b0;
    out[base + 2 * K + k] = b1;
}

__global__ void cat2(const float* __restrict__ a, const float* __restrict__ b,
                     float* __restrict__ o, int n) {
    int i = blockIdx.x * blockDim.x + threadIdx.x;
    if (i < n) { o[i] = a[i]; o[n + i] = b[i]; }
}

// ---------------- HMMA bf16 GEMM ----------------
// CTA tile 128x128, warp tile 32x64 (8 warps, 4x2), K-chunk 64, 3-stage cp.async.
// moff: row-block offset (for M-chunked pipelining).
#define STAGE_BYTES 32768   // 16KB A + 16KB B

__global__ __launch_bounds__(256, 2)
void gemm_mma(const __nv_bfloat16* __restrict__ A, const __nv_bfloat16* __restrict__ B,
              const float* __restrict__ bias, float* __restrict__ Cl,
              float* __restrict__ Cr,
              int M, int KsA, int KsB, int Nn, int Wn, int moff) {
    extern __shared__ __align__(1024) char sm[];
    int tid = threadIdx.x;
    int wid = tid >> 5, lane = tid & 31;
    int m0 = (blockIdx.y + moff) * 128, n0 = blockIdx.x * 128;
    int wm = wid >> 1, wn = wid & 1;
    uint32_t smb = smem_to_u32(sm);

    float acc[2][8][4];
#pragma unroll
    for (int t = 0; t < 2; t++)
#pragma unroll
        for (int j = 0; j < 8; j++)
#pragma unroll
            for (int q = 0; q < 4; q++) acc[t][j][q] = 0.f;

    int nch = KsB / 64;
    int nchA = KsA / 64;

    auto issue_load = [&](int c, int s) {
        uint32_t base = smb + s * STAGE_BYTES;
        int ca = (c < nchA) ? c : c - nchA;   // reuse a0 chunks for the b1 section
#pragma unroll
        for (int r = 0; r < 4; r++) {
            int idx = tid + r * 256;
            int row = idx >> 3, j = idx & 7;
            const __nv_bfloat16* gp = A + (size_t)(m0 + row) * KsA + ca * 64 + j * 8;
            uint32_t sa = base + SWZ128(row * 128 + j * 16);
            int sz = (m0 + row < M) ? 16 : 0;
            asm volatile("cp.async.cg.shared.global [%0], [%1], 16, %2;"
                         :: "r"(sa), "l"(gp), "r"(sz));
        }
#pragma unroll
        for (int r = 0; r < 4; r++) {
            int idx = tid + r * 256;
            int row = idx >> 3, j = idx & 7;
            const __nv_bfloat16* gp = B + (size_t)(n0 + row) * KsB + c * 64 + j * 8;
            uint32_t sa = base + 16384 + SWZ128(row * 128 + j * 16);
            asm volatile("cp.async.cg.shared.global [%0], [%1], 16;"
                         :: "r"(sa), "l"(gp));
        }
        asm volatile("cp.async.commit_group;");
    };

    issue_load(0, 0);
    if (nch > 1) issue_load(1, 1);

    for (int c = 0; c < nch; c++) {
        if (c + 1 < nch) asm volatile("cp.async.wait_group 1;");
        else             asm volatile("cp.async.wait_group 0;");
        __syncthreads();
        if (c + 2 < nch) issue_load(c + 2, (c + 2) % 3);

        uint32_t ab = smb + (c % 3) * STAGE_BYTES;
        uint32_t bb = ab + 16384;
#pragma unroll
        for (int kk = 0; kk < 4; kk++) {
            uint32_t af[2][4];
#pragma unroll
            for (int t = 0; t < 2; t++) {
                int rl = 32 * wm + 16 * t + (lane & 15);
                uint32_t ad = ab + SWZ128(rl * 128 + kk * 32 + (lane >> 4) * 16);
                ldmatrix_x4(af[t], ad);
            }
            uint32_t bf[4][4];
#pragma unroll
            for (int p = 0; p < 4; p++) {
                int nl = 64 * wn + 16 * p + ((lane >> 4) << 3) + (lane & 7);
                uint32_t bd = bb + SWZ128(nl * 128 + kk * 32 + ((lane >> 3) & 1) * 16);
                ldmatrix_x4(bf[p], bd);
            }
#pragma unroll
            for (int t = 0; t < 2; t++)
#pragma unroll
                for (int j = 0; j < 8; j++)
                    mma16816(acc[t][j], af[t],
                             bf[j >> 1][(j & 1) * 2], bf[j >> 1][(j & 1) * 2 + 1]);
        }
    }

    // epilogue: split into compact Cl / Cr
    int cbase = n0 + 64 * wn;
    float* Cd = (cbase < Wn) ? Cl : Cr;
    int coff = (cbase < Wn) ? cbase : cbase - Wn;
#pragma unroll
    for (int t = 0; t < 2; t++) {
        int gr = m0 + 32 * wm + 16 * t + (lane >> 2);
#pragma unroll
        for (int j = 0; j < 8; j++) {
            int gc = coff + 8 * j + (lane & 3) * 2;
            float2 bi = *(const float2*)(bias + cbase + 8 * j + (lane & 3) * 2);
            if (gr < M) {
                float2 o = make_float2(acc[t][j][0] + bi.x, acc[t][j][1] + bi.y);
                *(float2*)(Cd + (size_t)gr * Wn + gc) = o;
            }
            if (gr + 8 < M) {
                float2 o = make_float2(acc[t][j][2] + bi.x, acc[t][j][3] + bi.y);
                *(float2*)(Cd + (size_t)(gr + 8) * Wn + gc) = o;
            }
        }
    }
}

// ---------------- BN prep ----------------
__global__ void bn_prep(const float* __restrict__ bias, const float* __restrict__ g,
                        const float* __restrict__ b, const float* __restrict__ m,
                        const float* __restrict__ v, float* __restrict__ s,
                        float* __restrict__ t, int n) {
    int i = blockIdx.x * blockDim.x + threadIdx.x;
    if (i < n) {
        float sc = g[i] * rsqrtf(v[i] + BN_EPS);
        s[i] = sc;
        t[i] = b[i] + (bias[i] - m[i]) * sc;
    }
}

// ---------------- CSR build ----------------
__global__ void deg_zero(int* deg) {
    int i = blockIdx.x * blockDim.x + threadIdx.x;
    if (i < N_NODES) deg[i] = 0;
}
__global__ void deg_hist(const int* __restrict__ ei, int* __restrict__ deg) {
    int i = blockIdx.x * blockDim.x + threadIdx.x;
    if (i >= ETOT) return;
    int dst = (i < N_EDGES) ? ei[N_EDGES + i] : (i - N_EDGES);
    atomicAdd(&deg[dst], 1);
}
__global__ void scan_kernel(const int* __restrict__ deg, int* __restrict__ off,
                            int* __restrict__ cursor) {
    __shared__ int warp_sums[32];
    const int T = 1024;
    int tid = threadIdx.x;
    int chunk = (N_NODES + T - 1) / T;
    int start = tid * chunk;
    int end = min(start + chunk, N_NODES);
    int local = 0;
    for (int i = start; i < end; i++) local += deg[i];
    int lane = tid & 31, wid = tid >> 5;
    int v = local;
#pragma unroll
    for (int o = 1; o < 32; o <<= 1) {
        int u = __shfl_up_sync(0xFFFFFFFFu, v, o);
        if (lane >= o) v += u;
    }
    if (lane == 31) warp_sums[wid] = v;
    __syncthreads();
    if (wid == 0) {
        int s = warp_sums[lane];
#pragma unroll
        for (int o = 1; o < 32; o <<= 1) {
            int u = __shfl_up_sync(0xFFFFFFFFu, s, o);
            if (lane >= o) s += u;
        }
        warp_sums[lane] = s;
    }
    __syncthreads();
    int excl = v - local + (wid > 0 ? warp_sums[wid - 1] : 0);
    int run = excl;
    for (int i = start; i < end; i++) {
        off[i] = run;
        cursor[i] = run;
        run += deg[i];
    }
    if (tid == T - 1) off[N_NODES] = run;
}
__global__ void csr_scatter(const int* __restrict__ ei, int* __restrict__ cursor,
                            int* __restrict__ csr_src) {
    int i = blockIdx.x * blockDim.x + threadIdx.x;
    if (i >= ETOT) return;
    int src, dst;
    if (i < N_EDGES) { src = ei[i]; dst = ei[N_EDGES + i]; }
    else             { src = dst = i - N_EDGES; }
    int pos = atomicAdd(&cursor[dst], 1);
    csr_src[pos] = src;
}

// ---------------- fused GATv2 aggregation (one warp per dst node) --------------
// node range [node0, node1) for chunked pipelining.
template<int H, bool OUTBF16>
__global__ __launch_bounds__(256)
void fused_agg(const float* __restrict__ xl, const float* __restrict__ xr,
               const float* __restrict__ att,
               const int* __restrict__ off, const int* __restrict__ csr_src,
               const float* __restrict__ bns, const float* __restrict__ bnt,
               void* __restrict__ outp, int node0, int node1) {
    int node = node0 + ((blockIdx.x * blockDim.x + threadIdx.x) >> 5);
    int lane = threadIdx.x & 31;
    if (node >= node1) return;
    const int Wd = H * 128;

    const float4* xr4 = (const float4*)(xr + (size_t)node * Wd);
    const float4* at4 = (const float4*)att;

    float4 xrr[H], attr[H], acc[H];
    float m[H], sum[H];
#pragma unroll
    for (int h = 0; h < H; h++) {
        xrr[h]  = xr4[h * 32 + lane];
        attr[h] = at4[h * 32 + lane];
        acc[h]  = make_float4(0.f, 0.f, 0.f, 0.f);
        m[h]    = -INFINITY;
        sum[h]  = 0.f;
    }

    int e0 = off[node], e1 = off[node + 1];
    int src = csr_src[e0];
    float4 v[H];
    {
        const float4* xs = (const float4*)(xl + (size_t)src * Wd);
#pragma unroll
        for (int h = 0; h < H; h++) v[h] = xs[h * 32 + lane];
    }

    for (int e = e0; e < e1; e++) {
        int nsrc = (e + 1 < e1) ? csr_src[e + 1] : src;
        const float4* xn = (const float4*)(xl + (size_t)nsrc * Wd);
        float4 vn[H];
#pragma unroll
        for (int h = 0; h < H; h++) vn[h] = xn[h * 32 + lane];

#pragma unroll
        for (int h = 0; h < H; h++) {
            float ex = v[h].x + xrr[h].x; ex = ex > 0.f ? ex : 0.2f * ex;
            float ey = v[h].y + xrr[h].y; ey = ey > 0.f ? ey : 0.2f * ey;
            float ez = v[h].z + xrr[h].z; ez = ez > 0.f ? ez : 0.2f * ez;
            float ew = v[h].w + xrr[h].w; ew = ew > 0.f ? ew : 0.2f * ew;
            float s = ex * attr[h].x + ey * attr[h].y + ez * attr[h].z + ew * attr[h].w;
#pragma unroll
            for (int o = 16; o > 0; o >>= 1) s += __shfl_xor_sync(0xFFFFFFFFu, s, o);

            float mn = fmaxf(m[h], s);
            float c  = __expf(m[h] - mn);
            float p  = __expf(s - mn);
            sum[h]   = sum[h] * c + p;
            acc[h].x = acc[h].x * c + p * v[h].x;
            acc[h].y = acc[h].y * c + p * v[h].y;
            acc[h].z = acc[h].z * c + p * v[h].z;
            acc[h].w = acc[h].w * c + p * v[h].w;
            m[h] = mn;
        }
#pragma unroll
        for (int h = 0; h < H; h++) v[h] = vn[h];
    }

#pragma unroll
    for (int h = 0; h < H; h++) {
        int cbase = h * 128 + lane * 4;
        float4 sc = *(const float4*)(bns + cbase);
        float4 tt = *(const float4*)(bnt + cbase);
        float inv = 1.f / sum[h];
        float4 o;
        o.x = fmaxf(fmaf(acc[h].x * inv, sc.x, tt.x), 0.f);
        o.y = fmaxf(fmaf(acc[h].y * inv, sc.y, tt.y), 0.f);
        o.z = fmaxf(fmaf(acc[h].z * inv, sc.z, tt.z), 0.f);
        o.w = fmaxf(fmaf(acc[h].w * inv, sc.w, tt.w), 0.f);
        if (OUTBF16) {
            __nv_bfloat16* out = (__nv_bfloat16*)outp;
            size_t base = (size_t)node * (2 * Wd);
            __nv_bfloat16 h0x = __float2bfloat16(o.x), h0y = __float2bfloat16(o.y);
            __nv_bfloat16 h0z = __float2bfloat16(o.z), h0w = __float2bfloat16(o.w);
            __nv_bfloat16 h1x = __float2bfloat16(o.x - __bfloat162float(h0x));
            __nv_bfloat16 h1y = __float2bfloat16(o.y - __bfloat162float(h0y));
            __nv_bfloat16 h1z = __float2bfloat16(o.z - __bfloat162float(h0z));
            __nv_bfloat16 h1w = __float2bfloat16(o.w - __bfloat162float(h0w));
            uint2 p0, p1;
            p0.x = ((uint32_t)__bfloat16_as_ushort(h0y) << 16) | __bfloat16_as_ushort(h0x);
            p0.y = ((uint32_t)__bfloat16_as_ushort(h0w) << 16) | __bfloat16_as_ushort(h0z);
            p1.x = ((uint32_t)__bfloat16_as_ushort(h1y) << 16) | __bfloat16_as_ushort(h1x);
            p1.y = ((uint32_t)__bfloat16_as_ushort(h1w) << 16) | __bfloat16_as_ushort(h1z);
            *(uint2*)(out + base + cbase) = p0;
            *(uint2*)(out + base + Wd + cbase) = p1;
        } else {
            float* out = (float*)outp;
            *(float4*)(out + (size_t)node * Wd + cbase) = o;
        }
    }
}

// ---------------- prediction head ----------------
__global__ void head_kernel(const float* __restrict__ z, const int* __restrict__ pe,
                            const float* __restrict__ pr, const float* __restrict__ pert,
                            const float* __restrict__ Wp, const float* __restrict__ bp,
                            float* __restrict__ out) {
    __shared__ float sw[(W2 * 2 + 3) * 2];
    for (int i = threadIdx.x; i < (W2 * 2 + 3) * 2; i += blockDim.x) sw[i] = Wp[i];
    __syncthreads();

    int w = (blockIdx.x * blockDim.x + threadIdx.x) >> 5;
    int lane = threadIdx.x & 31;
    if (w >= N_PRED) return;
    int s = pe[w], d = pe[N_PRED + w];
    const float4* zs = (const float4*)(z + (size_t)s * W2);
    const float4* zd = (const float4*)(z + (size_t)d * W2);

    float a0 = 0.f, a1 = 0.f;
#pragma unroll
    for (int q = 0; q < 2; q++) {
        int r = lane * 2 + q;
        float4 vz = zs[r];
        int base = (r * 4) * 2;
        a0 += vz.x * sw[base] + vz.y * sw[base + 2] + vz.z * sw[base + 4] + vz.w * sw[base + 6];
        a1 += vz.x * sw[base + 1] + vz.y * sw[base + 3] + vz.z * sw[base + 5] + vz.w * sw[base + 7];
        float4 vd = zd[r];
        int base2 = (W2 + r * 4) * 2;
        a0 += vd.x * sw[base2] + vd.y * sw[base2 + 2] + vd.z * sw[base2 + 4] + vd.w * sw[base2 + 6];
        a1 += vd.x * sw[base2 + 1] + vd.y * sw[base2 + 3] + vd.z * sw[base2 + 5] + vd.w * sw[base2 + 7];
    }
    if (lane == 0) {
        float prs = pr[s], prd = pr[d], pp = pert[s] * pert[d];
        int b0 = (2 * W2) * 2;
        a0 += prs * sw[b0] + prd * sw[b0 + 2] + pp * sw[b0 + 4];
        a1 += prs * sw[b0 + 1] + prd * sw[b0 + 3] + pp * sw[b0 + 5];
    }
#pragma unroll
    for (int o = 16; o > 0; o >>= 1) {
        a0 += __shfl_xor_sync(0xFFFFFFFFu, a0, o);
        a1 += __shfl_xor_sync(0xFFFFFFFFu, a1, o);
    }
    if (lane == 0) {
        out[(size_t)w * 2 + 0] = a0 + bp[0];
        out[(size_t)w * 2 + 1] = a1 + bp[1];
    }
}

// ---------------- launch ----------------
extern "C" void kernel_launch(void* const* d_in, const int* in_sizes, int n_in,
                              void* d_out, int out_size) {
    const float* x     = (const float*)d_in[0];
    const int*   ei    = (const int*)d_in[1];
    const int*   pe    = (const int*)d_in[2];
    const float* pert  = (const float*)d_in[3];
    const float* pr    = (const float*)d_in[4];
    const float* Wl1   = (const float*)d_in[5];
    const float* bl1   = (const float*)d_in[6];
    const float* Wr1   = (const float*)d_in[7];
    const float* br1   = (const float*)d_in[8];
    const float* att1  = (const float*)d_in[9];
    const float* bias1 = (const float*)d_in[10];
    const float* bn1g  = (const float*)d_in[11];
    const float* bn1b  = (const float*)d_in[12];
    const float* bn1m  = (const float*)d_in[13];
    const float* bn1v  = (const float*)d_in[14];
    const float* Wl2   = (const float*)d_in[15];
    const float* bl2   = (const float*)d_in[16];
    const float* Wr2   = (const float*)d_in[17];
    const float* br2   = (const float*)d_in[18];
    const float* att2  = (const float*)d_in[19];
    const float* bias2 = (const float*)d_in[20];
    const float* bn2g  = (const float*)d_in[21];
    const float* bn2b  = (const float*)d_in[22];
    const float* bn2m  = (const float*)d_in[23];
    const float* bn2v  = (const float*)d_in[24];
    const float* Wp    = (const float*)d_in[25];
    const float* bp    = (const float*)d_in[26];
    float* out = (float*)d_out;

    float *xl1, *xr1, *xl2, *xr2, *z, *bc1, *bc2;
    float *bns1, *bnt1, *bns2, *bnt2;
    int *deg, *off, *cursor, *csr_src;
    __nv_bfloat16 *As1, *As2, *Wc1s, *Wc2s;
    cudaGetSymbolAddress((void**)&xl1, g_xl1);
    cudaGetSymbolAddress((void**)&xr1, g_xr1);
    cudaGetSymbolAddress((void**)&xl2, g_xl2);
    cudaGetSymbolAddress((void**)&xr2, g_xr2);
    cudaGetSymbolAddress((void**)&z,  g_z);
    cudaGetSymbolAddress((void**)&bc1, g_bc1);
    cudaGetSymbolAddress((void**)&bc2, g_bc2);
    cudaGetSymbolAddress((void**)&bns1, g_bns1);
    cudaGetSymbolAddress((void**)&bnt1, g_bnt1);
    cudaGetSymbolAddress((void**)&bns2, g_bns2);
    cudaGetSymbolAddress((void**)&bnt2, g_bnt2);
    cudaGetSymbolAddress((void**)&deg, g_deg);
    cudaGetSymbolAddress((void**)&off, g_off);
    cudaGetSymbolAddress((void**)&cursor, g_cursor);
    cudaGetSymbolAddress((void**)&csr_src, g_csr_src);
    cudaGetSymbolAddress((void**)&As1, g_As1);
    cudaGetSymbolAddress((void**)&As2, g_As2);
    cudaGetSymbolAddress((void**)&Wc1s, g_Wc1s);
    cudaGetSymbolAddress((void**)&Wc2s, g_Wc2s);

    static int s_init = 0;
    static cudaStream_t s_side;
    static cudaEvent_t s_evF, s_evJ, s_evA[NCHUNK], s_evG;
    if (!s_init) {
        cudaFuncSetAttribute(gemm_mma, cudaFuncAttributeMaxDynamicSharedMemorySize,
                             3 * STAGE_BYTES);
        cudaStreamCreateWithFlags(&s_side, cudaStreamNonBlocking);
        cudaEventCreateWithFlags(&s_evF, cudaEventDisableTiming);
        cudaEventCreateWithFlags(&s_evJ, cudaEventDisableTiming);
        cudaEventCreateWithFlags(&s_evG, cudaEventDisableTiming);
        for (int c = 0; c < NCHUNK; c++)
            cudaEventCreateWithFlags(&s_evA[c], cudaEventDisableTiming);
        s_init = 1;
    }

    const int TB = 256;
    int mblk = (N_NODES + 127) / 128;              // 391

    // ---- fork: side stream runs CSR + BN folding + layer-2 prep under GEMM1 ----
    cudaEventRecord(s_evF, 0);
    cudaStreamWaitEvent(s_side, s_evF, 0);

    deg_zero<<<(N_NODES + TB - 1) / TB, TB, 0, s_side>>>(deg);
    deg_hist<<<(ETOT + TB - 1) / TB, TB, 0, s_side>>>(ei, deg);
    scan_kernel<<<1, 1024, 0, s_side>>>(deg, off, cursor);
    csr_scatter<<<(ETOT + TB - 1) / TB, TB, 0, s_side>>>(ei, cursor, csr_src);
    bn_prep<<<(W1 + 255) / 256, 256, 0, s_side>>>(bias1, bn1g, bn1b, bn1m, bn1v,
                                                  bns1, bnt1, W1);
    bn_prep<<<(W2 + 255) / 256, 256, 0, s_side>>>(bias2, bn2g, bn2b, bn2m, bn2v,
                                                  bns2, bnt2, W2);
    cat2<<<(W2 + 255) / 256, 256, 0, s_side>>>(bl2, br2, bc2, W2);
    split_W_pair<<<(2 * K2 * W2 + TB - 1) / TB, TB, 0, s_side>>>(Wl2, Wr2, Wc2s, K2, W2);
    cudaEventRecord(s_evJ, s_side);

    // ---- main: layer-1 prep + GEMM1 ----
    cat2<<<(W1 + 255) / 256, 256>>>(bl1, br1, bc1, W1);
    split_A<<<(N_NODES * K1 + TB - 1) / TB, TB>>>(x, As1, N_NODES, K1);
    split_W_pair<<<(2 * K1 * W1 + TB - 1) / TB, TB>>>(Wl1, Wr1, Wc1s, K1, W1);
    {
        dim3 g1((2 * W1) / 128, mblk);
        gemm_mma<<<g1, 256, 3 * STAGE_BYTES>>>(As1, Wc1s, bc1, xl1, xr1,
                                               N_NODES, 2 * K1, 3 * K1, 2 * W1, W1, 0);
    }

    // ---- join side prep (CSR + bns1 + Wc2s/bc2) ----
    cudaStreamWaitEvent(0, s_evJ, 0);

    // ---- pipelined agg1 -> GEMM2 in NCHUNK M-chunks ----
    {
        int blk_per = (mblk + NCHUNK - 1) / NCHUNK;    // 98 row-blocks per chunk
        for (int c = 0; c < NCHUNK; c++) {
            int b0 = c * blk_per;
            int b1 = min(b0 + blk_per, mblk);
            if (b0 >= b1) break;
            int n0 = b0 * 128;
            int n1 = min(b1 * 128, N_NODES);
            int nwarp = n1 - n0;
            fused_agg<H1, true><<<(nwarp * 32 + TB - 1) / TB, TB>>>(
                xl1, xr1, att1, off, csr_src, bns1, bnt1, As2, n0, n1);
            cudaEventRecord(s_evA[c], 0);
            cudaStreamWaitEvent(s_side, s_evA[c], 0);
            dim3 g2((2 * W2) / 128, b1 - b0);
            gemm_mma<<<g2, 256, 3 * STAGE_BYTES, s_side>>>(
                As2, Wc2s, bc2, xl2, xr2, N_NODES, 2 * K2, 3 * K2, 2 * W2, W2, b0);
        }
        cudaEventRecord(s_evG, s_side);
        cudaStreamWaitEvent(0, s_evG, 0);
    }

    // ---- layer-2 aggregation + head ----
    {
        int nwarp_blk = (N_NODES * 32 + TB - 1) / TB;
        fused_agg<H2, false><<<nwarp_blk, TB>>>(xl2, xr2, att2,
                                                off, csr_src, bns2, bnt2, z,
                                                0, N_NODES);
    }
    head_kernel<<<(N_PRED * 32 + TB - 1) / TB, TB>>>(z, pe, pr, pert, Wp, bp, out);
}